// round 7
// baseline (speedup 1.0000x reference)
#include <cuda_runtime.h>
#include <cuda_bf16.h>
#include <math.h>
#include <float.h>
#include <stdint.h>

// Problem dims: B=8, S=32, HN=64, TN=512, HID=EMB=512
// ---------------- scratch (device globals; no allocation) ----------------
__device__ float g_dh  [256 * 1024];            // [.,0:512)=decp  [.,512:1024)=hqd
__device__ float g_hh  [8   * 1024];            // [.,0:512)=histp [.,512:1024)=hqh
__device__ float g_headq[512  * 512];
__device__ float g_attn [8LL*2048*512];
__device__ float g_hk   [16384LL*512];
__device__ float g_hq   [256 * 512];
__device__ __nv_bfloat16 g_tq_hi [8LL*2048*512], g_tq_lo [8LL*2048*512];
__device__ __nv_bfloat16 g_tk_hi [4096LL*512],   g_tk_lo [4096LL*512];
__device__ __nv_bfloat16 g_tkT_hi[4096LL*512],   g_tkT_lo[4096LL*512];
__device__ __nv_bfloat16 g_at_hi [8LL*2048*512], g_at_lo [8LL*2048*512];
__device__ __nv_bfloat16 g_ctx_hi[8LL*2048*512], g_ctx_lo[8LL*2048*512];
__device__ __nv_bfloat16 g_gh_hi [8LL*2048*512], g_gh_lo [8LL*2048*512];
__device__ __nv_bfloat16 g_wT_hi [9LL*512*512],  g_wT_lo [9LL*512*512];
__device__ unsigned int g_mask_byte_mode;

__device__ __forceinline__ uint32_t smem_u32(const void* p) {
    uint32_t a;
    asm("{ .reg .u64 t; cvta.to.shared.u64 t, %1; cvt.u32.u64 %0, t; }" : "=r"(a) : "l"(p));
    return a;
}
__device__ __forceinline__ void cp16(uint32_t dst, const void* src) {
    asm volatile("cp.async.cg.shared.global [%0], [%1], 16;" :: "r"(dst), "l"(src));
}
__device__ __forceinline__ void mma_bf16(float* d, const uint32_t* a, const uint32_t* b) {
    asm volatile("mma.sync.aligned.m16n8k16.row.col.f32.bf16.bf16.f32 "
        "{%0,%1,%2,%3}, {%4,%5,%6,%7}, {%8,%9}, {%0,%1,%2,%3};"
        : "+f"(d[0]), "+f"(d[1]), "+f"(d[2]), "+f"(d[3])
        : "r"(a[0]), "r"(a[1]), "r"(a[2]), "r"(a[3]), "r"(b[0]), "r"(b[1]));
}
__device__ __forceinline__ void ldm_x4(uint32_t& r0, uint32_t& r1, uint32_t& r2, uint32_t& r3,
                                       uint32_t addr) {
    asm volatile("ldmatrix.sync.aligned.m8n8.x4.shared.b16 {%0,%1,%2,%3}, [%4];"
        : "=r"(r0), "=r"(r1), "=r"(r2), "=r"(r3) : "r"(addr));
}
__device__ __forceinline__ float eluf(float x) { return x > 0.f ? x : expm1f(x); }

// smem: three buffers; each buffer = A tile (128 rows x 144B) + B tile (128 x 144B)
// row layout: bytes [0,64) = hi 32 bf16, [64,128) = lo 32 bf16, [128,144) pad
#define ROWB   144
#define TILEB  (128 * ROWB)          // 18432
#define BUFB   (2 * TILEB)           // 36864 (A + B)
#define NSTAGE 3
#define SMEM_BYTES (NSTAGE * BUFB)   // 110592

// ==================================================================
// bf16-split GEMM via mma.sync + ldmatrix, 3-stage cp.async pipeline
// C[M, Ngrid] = act(A[M,K] @ B[Ngrid,K]^T (+pair2) + bias), ldc = C row stride
// MT:   M tile (128 or 64)
// ASRC: 0 = A pre-split bf16 hi/lo; 1 = gather fp32 rows of Af by gidx; 2 = fp32 rows
// TWO:  accumulate second (A2,B2) pair (same K)
// OUTB: write bf16 hi/lo, else fp32.  ACT: 0 none, 1 elu, 2 tanh
// ChiT/CloT non-null (OUTB only): also write per-512-row-batch transposed copy
// ==================================================================
template<int MT, int ACT, int ASRC, bool TWO, bool OUTB>
__global__ void __launch_bounds__(256) gemm_mma(
    const __nv_bfloat16* __restrict__ Ahi, const __nv_bfloat16* __restrict__ Alo,
    const float* __restrict__ Af, const int* __restrict__ gidx,
    const __nv_bfloat16* __restrict__ Bhi, const __nv_bfloat16* __restrict__ Blo,
    const __nv_bfloat16* __restrict__ A2hi, const __nv_bfloat16* __restrict__ A2lo,
    const __nv_bfloat16* __restrict__ B2hi, const __nv_bfloat16* __restrict__ B2lo,
    float* __restrict__ Cf, __nv_bfloat16* __restrict__ Chi, __nv_bfloat16* __restrict__ Clo,
    __nv_bfloat16* __restrict__ ChiT, __nv_bfloat16* __restrict__ CloT,
    const float* __restrict__ bias,
    int M, int K, long long sA, long long sB, long long sC, int ldc)
{
    constexpr int FM = MT / 32;                     // frag rows per warp
    extern __shared__ char sm[];
    const uint32_t smb = smem_u32(sm);
    const int tid = threadIdx.x, wid = tid >> 5, lane = tid & 31;
    const int wm = wid >> 2, wn = wid & 3;          // warp grid 2 (m) x 4 (n)
    const int m0 = blockIdx.y * MT, n0 = blockIdx.x * 128, z = blockIdx.z;

    const int kc  = K >> 5;                         // chunks of 32 fp32-k
    const int nch = TWO ? 2 * kc : kc;

    float d[FM][4][4];
    #pragma unroll
    for (int f = 0; f < FM; f++)
        #pragma unroll
        for (int g = 0; g < 4; g++)
            #pragma unroll
            for (int e = 0; e < 4; e++) d[f][g][e] = 0.f;

    auto load_chunk = [&](int c) {
        const bool sec = TWO && (c >= kc);
        const int koff = (sec ? c - kc : c) << 5;   // fp32-k offset
        const int buf = c % NSTAGE;
        const uint32_t smA = smb + buf * BUFB;
        const uint32_t smB = smA + TILEB;
        char* smAp = sm + buf * BUFB;

        // ---- A (MT rows) ----
        if constexpr (ASRC == 0) {
            const __nv_bfloat16* pH = (sec ? A2hi : Ahi) + (long long)z * sA;
            const __nv_bfloat16* pL = (sec ? A2lo : Alo) + (long long)z * sA;
            #pragma unroll
            for (int i = 0; i < MT * 4 / 256; i++) {
                const int idx = tid + 256 * i;
                const int r = idx >> 2, s = idx & 3;
                const long long go = (long long)(m0 + r) * K + koff + s * 8;
                const uint32_t dh = smA + r * ROWB + s * 16;
                cp16(dh,      pH + go);
                cp16(dh + 64, pL + go);
            }
        } else {
            #pragma unroll
            for (int i = 0; i < MT * 8 / 256; i++) {
                const int idx = tid + 256 * i;
                const int r = idx >> 3, s = idx & 7;
                const int gm = m0 + r;
                float4 v = make_float4(0.f, 0.f, 0.f, 0.f);
                if (gm < M) {
                    const long long row = (ASRC == 1) ? (long long)gidx[gm] : (long long)gm;
                    v = *reinterpret_cast<const float4*>(Af + row * K + koff + s * 4);
                }
                __nv_bfloat162 h01 = __floats2bfloat162_rn(v.x, v.y);
                __nv_bfloat162 h23 = __floats2bfloat162_rn(v.z, v.w);
                float2 f01 = __bfloat1622float2(h01), f23 = __bfloat1622float2(h23);
                __nv_bfloat162 l01 = __floats2bfloat162_rn(v.x - f01.x, v.y - f01.y);
                __nv_bfloat162 l23 = __floats2bfloat162_rn(v.z - f23.x, v.w - f23.y);
                uint2 uh, ul;
                uh.x = *(uint32_t*)&h01; uh.y = *(uint32_t*)&h23;
                ul.x = *(uint32_t*)&l01; ul.y = *(uint32_t*)&l23;
                *reinterpret_cast<uint2*>(smAp + r * ROWB + s * 8)      = uh;
                *reinterpret_cast<uint2*>(smAp + r * ROWB + 64 + s * 8) = ul;
            }
        }
        // ---- B (always 128 rows, pre-split bf16) ----
        {
            const __nv_bfloat16* pH = (sec ? B2hi : Bhi) + (long long)z * sB;
            const __nv_bfloat16* pL = (sec ? B2lo : Blo) + (long long)z * sB;
            #pragma unroll
            for (int i = 0; i < 2; i++) {
                const int idx = tid + 256 * i;
                const int r = idx >> 2, s = idx & 3;
                const long long go = (long long)(n0 + r) * K + koff + s * 8;
                const uint32_t dh = smB + r * ROWB + s * 16;
                cp16(dh,      pH + go);
                cp16(dh + 64, pL + go);
            }
        }
        asm volatile("cp.async.commit_group;");
    };

    load_chunk(0);
    if (nch > 1) load_chunk(1);

    // bf16-col offsets for the 6 k16 steps: AhBh, AhBl, AlBh
    const int stepA[6] = {0, 16, 0, 16, 32, 48};
    const int stepB[6] = {0, 16, 32, 48, 0, 16};

    // ldmatrix lane mapping (non-trans x4, matrices in lane-octet order)
    const int lrow = lane & 7, lsel = lane >> 3;
    const int a_dm = (lsel & 1) << 3, a_dk = (lsel >> 1) << 3;
    const int b_dn = (lsel >> 1) << 3, b_dk = (lsel & 1) << 3;

    for (int c = 0; c < nch; ++c) {
        if (c + 2 < nch) load_chunk(c + 2);
        const int rem = nch - 1 - c;
        if (rem >= 2)      asm volatile("cp.async.wait_group 2;");
        else if (rem == 1) asm volatile("cp.async.wait_group 1;");
        else               asm volatile("cp.async.wait_group 0;");
        __syncthreads();

        const uint32_t a_base = smb + (c % NSTAGE) * BUFB;
        const uint32_t b_base = a_base + TILEB;

        #pragma unroll
        for (int st = 0; st < 6; ++st) {
            const int ka = stepA[st], kb = stepB[st];
            uint32_t a[FM][4], b[4][2];
            #pragma unroll
            for (int f = 0; f < FM; f++) {
                const uint32_t addr = a_base
                    + (uint32_t)((wm * (MT/2) + f * 16 + a_dm + lrow) * ROWB + (ka + a_dk) * 2);
                ldm_x4(a[f][0], a[f][1], a[f][2], a[f][3], addr);
            }
            #pragma unroll
            for (int gp = 0; gp < 2; gp++) {
                const uint32_t addr = b_base
                    + (uint32_t)((wn * 32 + gp * 16 + b_dn + lrow) * ROWB + (kb + b_dk) * 2);
                ldm_x4(b[2*gp][0], b[2*gp][1], b[2*gp+1][0], b[2*gp+1][1], addr);
            }
            #pragma unroll
            for (int f = 0; f < FM; f++)
                #pragma unroll
                for (int g = 0; g < 4; g++)
                    mma_bf16(d[f][g], a[f], b[g]);
        }
        __syncthreads();
    }

    // ---- epilogue: fragments -> gmem with fused bias/act (+bf16 split, +T copy) ----
    const int qr = lane >> 2, qc = 2 * (lane & 3);
    #pragma unroll
    for (int f = 0; f < FM; f++) {
        #pragma unroll
        for (int g = 0; g < 4; g++) {
            const int cc = n0 + wn * 32 + g * 8 + qc;
            float bx = 0.f, by = 0.f;
            if (bias) { bx = bias[cc]; by = bias[cc + 1]; }
            #pragma unroll
            for (int h = 0; h < 2; h++) {
                const int row = m0 + wm * (MT/2) + f * 16 + qr + h * 8;
                if (row >= M) continue;
                float v0 = d[f][g][2 * h]     + bx;
                float v1 = d[f][g][2 * h + 1] + by;
                if (ACT == 1) { v0 = eluf(v0); v1 = eluf(v1); }
                else if (ACT == 2) { v0 = tanhf(v0); v1 = tanhf(v1); }
                const long long o = (long long)z * sC + (long long)row * ldc + cc;
                if constexpr (!OUTB) {
                    *reinterpret_cast<float2*>(Cf + o) = make_float2(v0, v1);
                } else {
                    __nv_bfloat162 hb = __floats2bfloat162_rn(v0, v1);
                    float2 hf = __bfloat1622float2(hb);
                    __nv_bfloat162 lb = __floats2bfloat162_rn(v0 - hf.x, v1 - hf.y);
                    *reinterpret_cast<__nv_bfloat162*>(Chi + o) = hb;
                    *reinterpret_cast<__nv_bfloat162*>(Clo + o) = lb;
                    if (ChiT) {
                        const int bb = row >> 9, t = row & 511;
                        const long long zt = (long long)bb * 262144 + t;
                        ChiT[zt + (long long)cc * 512]       = __low2bfloat16(hb);
                        ChiT[zt + (long long)(cc + 1) * 512] = __high2bfloat16(hb);
                        CloT[zt + (long long)cc * 512]       = __low2bfloat16(lb);
                        CloT[zt + (long long)(cc + 1) * 512] = __high2bfloat16(lb);
                    }
                }
            }
        }
    }
}

// ---------------- weights: transpose 512x512 fp32 -> bf16 hi/lo ----------------
struct WPtrs { const float* s[9]; };
__global__ void prep_weights(WPtrs wp, __nv_bfloat16* __restrict__ dhi, __nv_bfloat16* __restrict__ dlo)
{
    __shared__ float t[32][33];
    const int mtx = blockIdx.z;
    const float* src = wp.s[mtx];
    __nv_bfloat16* oh = dhi + (long long)mtx * 512 * 512;
    __nv_bfloat16* ol = dlo + (long long)mtx * 512 * 512;
    const int tx = threadIdx.x, ty = threadIdx.y;
    const int bx = blockIdx.x * 32, by = blockIdx.y * 32;
    #pragma unroll
    for (int i = 0; i < 32; i += 8)
        t[ty + i][tx] = src[(long long)(by + ty + i) * 512 + bx + tx];
    __syncthreads();
    #pragma unroll
    for (int i = 0; i < 32; i += 8) {
        const float v = t[tx][ty + i];
        const __nv_bfloat16 h = __float2bfloat16(v);
        const long long o = (long long)(bx + ty + i) * 512 + by + tx;
        oh[o] = h;
        ol[o] = __float2bfloat16(v - __bfloat162float(h));
    }
}

// ---------------- history small GEMM: out[8][1024] = hist @ [Wh | Whq1] ----------------
__global__ void hist_small(const float* __restrict__ hist,
                           const __nv_bfloat16* __restrict__ w7h, const __nv_bfloat16* __restrict__ w7l,
                           const __nv_bfloat16* __restrict__ w8h, const __nv_bfloat16* __restrict__ w8l,
                           float* __restrict__ out)
{
    const int wid = threadIdx.x >> 5, lane = threadIdx.x & 31;
    const int c = blockIdx.x * 8 + wid;             // 0..1023
    const __nv_bfloat16* rh = (c < 512) ? w7h + (long long)c * 512 : w8h + (long long)(c - 512) * 512;
    const __nv_bfloat16* rl = (c < 512) ? w7l + (long long)c * 512 : w8l + (long long)(c - 512) * 512;
    float acc[8] = {0.f,0.f,0.f,0.f,0.f,0.f,0.f,0.f};
    #pragma unroll 4
    for (int i = 0; i < 16; i++) {
        const int k = lane + i * 32;
        const float w = __bfloat162float(rh[k]) + __bfloat162float(rl[k]);
        #pragma unroll
        for (int r = 0; r < 8; r++) acc[r] = fmaf(hist[r * 512 + k], w, acc[r]);
    }
    #pragma unroll
    for (int r = 0; r < 8; r++) {
        float v = acc[r];
        #pragma unroll
        for (int o = 16; o; o >>= 1) v += __shfl_xor_sync(0xffffffffu, v, o);
        if (lane == 0) out[r * 1024 + c] = v;
    }
}

// ---------------- mask dtype detector ----------------
__global__ void detect_mask_kernel(const unsigned int* __restrict__ adj, int nwords)
{
    __shared__ unsigned int s;
    if (threadIdx.x == 0) s = 0u;
    __syncthreads();
    unsigned int local = 0u;
    for (int i = threadIdx.x; i < nwords; i += blockDim.x)
        local |= (adj[i] > 1u) ? 1u : 0u;
    if (local) atomicOr(&s, 1u);
    __syncthreads();
    if (threadIdx.x == 0) g_mask_byte_mode = s;
}

// ---------------- tq = elu(decp + histp + headq + b_tq) -> bf16 hi/lo ----------------
__global__ void build_tq(const float4* __restrict__ dh, const float4* __restrict__ hh,
                         const float4* __restrict__ headq, const float4* __restrict__ btq,
                         __nv_bfloat162* __restrict__ thi, __nv_bfloat162* __restrict__ tlo)
{
    const int i = blockIdx.x * 256 + threadIdx.x;
    const int d  = i & 127;
    const int h  = (i >> 7) & 63;
    const int bs = i >> 13;
    const int b  = bs >> 5;
    float4 a = dh[bs * 256 + d];
    float4 c = hh[b * 256 + d];
    float4 e = headq[(b * 64 + h) * 128 + d];
    float4 g = btq[d];
    float4 r;
    r.x = eluf(a.x + c.x + e.x + g.x);
    r.y = eluf(a.y + c.y + e.y + g.y);
    r.z = eluf(a.z + c.z + e.z + g.z);
    r.w = eluf(a.w + c.w + e.w + g.w);
    __nv_bfloat162 h0 = __floats2bfloat162_rn(r.x, r.y);
    __nv_bfloat162 h1 = __floats2bfloat162_rn(r.z, r.w);
    float2 f0 = __bfloat1622float2(h0), f1 = __bfloat1622float2(h1);
    __nv_bfloat162 l0 = __floats2bfloat162_rn(r.x - f0.x, r.y - f0.y);
    __nv_bfloat162 l1 = __floats2bfloat162_rn(r.z - f1.x, r.w - f1.y);
    thi[2 * i] = h0; thi[2 * i + 1] = h1;
    tlo[2 * i] = l0; tlo[2 * i + 1] = l1;
}

// ---------------- hq = elu(hqd + hqh + b_hq) (cols 512:1024) ----------------
__global__ void build_hq(const float4* __restrict__ dh, const float4* __restrict__ hh,
                         const float4* __restrict__ bhq, float4* __restrict__ hq)
{
    const int i = blockIdx.x * 256 + threadIdx.x;   // 0..32767
    const int d  = i & 127;
    const int bs = i >> 7;
    const int b  = bs >> 5;
    float4 a = dh[bs * 256 + 128 + d];
    float4 c = hh[b * 256 + 128 + d];
    float4 g = bhq[d];
    float4 r;
    r.x = eluf(a.x + c.x + g.x);
    r.y = eluf(a.y + c.y + g.y);
    r.z = eluf(a.z + c.z + g.z);
    r.w = eluf(a.w + c.w + g.w);
    hq[i] = r;
}

// ---------------- masked softmax (fp32 in place + bf16 hi/lo out) ----------------
__global__ void masked_softmax(float* __restrict__ attn,
                               __nv_bfloat16* __restrict__ ahi, __nv_bfloat16* __restrict__ alo,
                               const void* __restrict__ adj, const void* __restrict__ dup)
{
    const int q = blockIdx.x;
    const int b = blockIdx.y;
    const int s = q >> 6, h = q & 63;
    const long long ro = ((long long)(b * 2048 + q)) * 512;
    float* row = attn + ro;
    const long long aoff = ((long long)(b * 64 + h)) * 512;
    const long long doff = ((long long)(b * 32 + s)) * 512;

    const unsigned int byte_mode = g_mask_byte_mode;
    const unsigned char* am8 = (const unsigned char*)adj + aoff;
    const unsigned char* dm8 = (const unsigned char*)dup + doff;
    const int* am32 = (const int*)adj + aoff;
    const int* dm32 = (const int*)dup + doff;

    const int tid = threadIdx.x;
    float v[2]; int mk[2];
    float lmax = -FLT_MAX;
    #pragma unroll
    for (int j = 0; j < 2; j++) {
        const int t = tid + j * 256;
        if (byte_mode) mk[j] = am8[t]  && !dm8[t];
        else           mk[j] = am32[t] && !dm32[t];
        v[j] = row[t];
        if (mk[j]) lmax = fmaxf(lmax, v[j]);
    }
    __shared__ float smax[8], ssum[8];
    #pragma unroll
    for (int o = 16; o; o >>= 1) lmax = fmaxf(lmax, __shfl_xor_sync(0xffffffffu, lmax, o));
    if ((tid & 31) == 0) smax[tid >> 5] = lmax;
    __syncthreads();
    float bmax = -FLT_MAX;
    #pragma unroll
    for (int w = 0; w < 8; w++) bmax = fmaxf(bmax, smax[w]);

    float e[2], lsum = 0.f;
    #pragma unroll
    for (int j = 0; j < 2; j++) { e[j] = mk[j] ? expf(v[j] - bmax) : 0.f; lsum += e[j]; }
    #pragma unroll
    for (int o = 16; o; o >>= 1) lsum += __shfl_xor_sync(0xffffffffu, lsum, o);
    if ((tid & 31) == 0) ssum[tid >> 5] = lsum;
    __syncthreads();
    float bsum = 0.f;
    #pragma unroll
    for (int w = 0; w < 8; w++) bsum += ssum[w];

    const float inv = 1.f / bsum;
    #pragma unroll
    for (int j = 0; j < 2; j++) {
        const int t = tid + j * 256;
        const float p = e[j] * inv;
        row[t] = p;
        const __nv_bfloat16 hb = __float2bfloat16(p);
        ahi[ro + t] = hb;
        alo[ro + t] = __float2bfloat16(p - __bfloat162float(hb));
    }
}

// ---------------- final: head attention + prob + log ----------------
__global__ void final_kernel(const float* __restrict__ hq, const float* __restrict__ hk,
                             const float* __restrict__ attn, const int* __restrict__ head,
                             float* __restrict__ out)
{
    const int n = blockIdx.x;
    const int b = n >> 5;
    const int tid = threadIdx.x;

    __shared__ float shq[512];
    __shared__ float sc[64];
    __shared__ float sw[64];
    __shared__ int   s_len;

    if (tid == 0) s_len = 0;
    shq[tid]       = hq[(long long)n * 512 + tid];
    shq[tid + 256] = hq[(long long)n * 512 + 256 + tid];
    __syncthreads();
    if (tid < 64) { if (head[b * 64 + tid] != 0) atomicAdd(&s_len, 1); }
    __syncthreads();

    const int w = tid >> 5, lane = tid & 31;
    for (int k = w; k < 64; k += 8) {
        const float* hkr = hk + ((long long)n * 64 + k) * 512;
        float sacc = 0.f;
        for (int d = lane; d < 512; d += 32) sacc = fmaf(shq[d], hkr[d], sacc);
        #pragma unroll
        for (int o = 16; o; o >>= 1) sacc += __shfl_xor_sync(0xffffffffu, sacc, o);
        if (lane == 0) sc[k] = sacc;
    }
    __syncthreads();

    if (tid == 0) {
        const int len = s_len;
        float mx = -FLT_MAX;
        for (int k = 0; k < len; k++) mx = fmaxf(mx, sc[k]);
        float sum = 0.f;
        for (int k = 0; k < 64; k++) {
            float e = (k < len) ? expf(sc[k] - mx) : 0.f;
            sw[k] = e; sum += e;
        }
        float inv = 1.f / sum;
        for (int k = 0; k < 64; k++) sw[k] *= inv;
    }
    __syncthreads();

    const float* at = attn + (long long)n * 64 * 512;
    for (int t = tid; t < 512; t += 256) {
        float p = 0.f;
        #pragma unroll 8
        for (int k = 0; k < 64; k++) p = fmaf(sw[k], at[k * 512 + t], p);
        out[(long long)n * 512 + t] = logf(p + 1e-20f);
    }
}

// ---------------- launch ----------------
extern "C" void kernel_launch(void* const* d_in, const int* in_sizes, int n_in,
                              void* d_out, int out_size)
{
    const float* dec_out = (const float*)d_in[0];
    const float* history = (const float*)d_in[1];
    const int*   head    = (const int*)  d_in[2];
    const int*   tail    = (const int*)  d_in[3];
    const void*  adj     = d_in[4];
    const void*  dup     = d_in[5];
    const float* emb     = (const float*)d_in[6];
    const float* W_tq    = (const float*)d_in[7];
    const float* b_tq    = (const float*)d_in[8];
    const float* W_tk    = (const float*)d_in[9];
    const float* b_tk    = (const float*)d_in[10];
    const float* W_tout  = (const float*)d_in[11];
    const float* W_hq    = (const float*)d_in[12];
    const float* b_hq    = (const float*)d_in[13];
    const float* W_hk    = (const float*)d_in[14];
    const float* b_hk    = (const float*)d_in[15];

    float *dh, *hh, *headq, *attn, *hk, *hq;
    __nv_bfloat16 *tq_hi, *tq_lo, *tk_hi, *tk_lo, *tkT_hi, *tkT_lo;
    __nv_bfloat16 *at_hi, *at_lo, *ctx_hi, *ctx_lo, *gh_hi, *gh_lo, *wT_hi, *wT_lo;
    cudaGetSymbolAddress((void**)&dh,     g_dh);
    cudaGetSymbolAddress((void**)&hh,     g_hh);
    cudaGetSymbolAddress((void**)&headq,  g_headq);
    cudaGetSymbolAddress((void**)&attn,   g_attn);
    cudaGetSymbolAddress((void**)&hk,     g_hk);
    cudaGetSymbolAddress((void**)&hq,     g_hq);
    cudaGetSymbolAddress((void**)&tq_hi,  g_tq_hi);  cudaGetSymbolAddress((void**)&tq_lo,  g_tq_lo);
    cudaGetSymbolAddress((void**)&tk_hi,  g_tk_hi);  cudaGetSymbolAddress((void**)&tk_lo,  g_tk_lo);
    cudaGetSymbolAddress((void**)&tkT_hi, g_tkT_hi); cudaGetSymbolAddress((void**)&tkT_lo, g_tkT_lo);
    cudaGetSymbolAddress((void**)&at_hi,  g_at_hi);  cudaGetSymbolAddress((void**)&at_lo,  g_at_lo);
    cudaGetSymbolAddress((void**)&ctx_hi, g_ctx_hi); cudaGetSymbolAddress((void**)&ctx_lo, g_ctx_lo);
    cudaGetSymbolAddress((void**)&gh_hi,  g_gh_hi);  cudaGetSymbolAddress((void**)&gh_lo,  g_gh_lo);
    cudaGetSymbolAddress((void**)&wT_hi,  g_wT_hi);  cudaGetSymbolAddress((void**)&wT_lo,  g_wT_lo);

    cudaFuncSetAttribute(gemm_mma<64 ,0,2,false,false>, cudaFuncAttributeMaxDynamicSharedMemorySize, SMEM_BYTES);
    cudaFuncSetAttribute(gemm_mma<64 ,0,1,false,false>, cudaFuncAttributeMaxDynamicSharedMemorySize, SMEM_BYTES);
    cudaFuncSetAttribute(gemm_mma<128,1,1,false,true >, cudaFuncAttributeMaxDynamicSharedMemorySize, SMEM_BYTES);
    cudaFuncSetAttribute(gemm_mma<128,0,0,false,false>, cudaFuncAttributeMaxDynamicSharedMemorySize, SMEM_BYTES);
    cudaFuncSetAttribute(gemm_mma<128,0,0,false,true >, cudaFuncAttributeMaxDynamicSharedMemorySize, SMEM_BYTES);
    cudaFuncSetAttribute(gemm_mma<128,2,0,true ,true >, cudaFuncAttributeMaxDynamicSharedMemorySize, SMEM_BYTES);
    cudaFuncSetAttribute(gemm_mma<128,1,0,false,false>, cudaFuncAttributeMaxDynamicSharedMemorySize, SMEM_BYTES);

    // weight slots: 0 Wd, 1 Whq0 (merged N=1024), 2 We, 3 Wtk, 4 Wtout0, 5 Wtout1,
    //               6 Whk, 7 Wh, 8 Whq1 (7/8 consumed by hist_small)
    WPtrs wp;
    wp.s[0] = W_tq;               wp.s[1] = W_hq;               wp.s[2] = W_tq + 1024LL*512;
    wp.s[3] = W_tk;               wp.s[4] = W_tout;             wp.s[5] = W_tout + 512LL*512;
    wp.s[6] = W_hk;               wp.s[7] = W_tq + 512LL*512;   wp.s[8] = W_hq + 512LL*512;
    #define WTH(i) (wT_hi + (long long)(i)*512*512)
    #define WTL(i) (wT_lo + (long long)(i)*512*512)

    detect_mask_kernel<<<1, 256>>>((const unsigned int*)adj, 65536);
    prep_weights<<<dim3(16,16,9), dim3(32,8)>>>(wp, wT_hi, wT_lo);

    const __nv_bfloat16* nb = nullptr;
    __nv_bfloat16* nbm = nullptr;

    // hh = history @ [Wh | Whq1]  (8 x 1024)
    hist_small<<<128, 256>>>(history, WTH(7), WTL(7), WTH(8), WTL(8), hh);
    // dh = dec_out @ [Wd | Whq0]  (256 x 1024), MT=64
    gemm_mma<64,0,2,false,false><<<dim3(8,4,1), 256, SMEM_BYTES>>>(
        nb, nb, dec_out, nullptr, WTH(0), WTL(0), nb, nb, nb, nb,
        dh, nullptr, nullptr, nbm, nbm, nullptr, 256, 512, 0, 0, 0, 1024);
    // headq = emb[head] @ We (M=512), MT=64
    gemm_mma<64,0,1,false,false><<<dim3(4,8,1), 256, SMEM_BYTES>>>(
        nb, nb, emb, head, WTH(2), WTL(2), nb, nb, nb, nb,
        headq, nullptr, nullptr, nbm, nbm, nullptr, 512, 512, 0, 0, 0, 512);
    // tk = elu(emb[tail] @ Wtk + b_tk) -> bf16 + fused per-batch transpose (M=4096)
    gemm_mma<128,1,1,false,true><<<dim3(4,32,1), 256, SMEM_BYTES>>>(
        nb, nb, emb, tail, WTH(3), WTL(3), nb, nb, nb, nb,
        nullptr, tk_hi, tk_lo, tkT_hi, tkT_lo, b_tk, 4096, 512, 0, 0, 0, 512);
    build_tq<<<8192, 256>>>((const float4*)dh, (const float4*)hh,
                            (const float4*)headq, (const float4*)b_tq,
                            (__nv_bfloat162*)tq_hi, (__nv_bfloat162*)tq_lo);
    // scores[b] = tq[b] @ tk[b]^T  (M=2048 per batch)
    gemm_mma<128,0,0,false,false><<<dim3(4,16,8), 256, SMEM_BYTES>>>(
        tq_hi, tq_lo, nullptr, nullptr, tk_hi, tk_lo, nb, nb, nb, nb,
        attn, nullptr, nullptr, nbm, nbm, nullptr, 2048, 512,
        2048LL*512, 512LL*512, 2048LL*512, 512);
    masked_softmax<<<dim3(2048,8), 256>>>(attn, at_hi, at_lo, adj, dup);
    // ctx[b] = attn[b] @ tk[b] -> bf16
    gemm_mma<128,0,0,false,true><<<dim3(4,16,8), 256, SMEM_BYTES>>>(
        at_hi, at_lo, nullptr, nullptr, tkT_hi, tkT_lo, nb, nb, nb, nb,
        nullptr, ctx_hi, ctx_lo, nbm, nbm, nullptr, 2048, 512,
        2048LL*512, 512LL*512, 2048LL*512, 512);
    // ghid = tanh(ctx @ Wtout0 + tq @ Wtout1) -> bf16 (M=16384)
    gemm_mma<128,2,0,true,true><<<dim3(4,128,1), 256, SMEM_BYTES>>>(
        ctx_hi, ctx_lo, nullptr, nullptr, WTH(4), WTL(4),
        tq_hi, tq_lo, WTH(5), WTL(5),
        nullptr, gh_hi, gh_lo, nbm, nbm, nullptr, 16384, 512, 0, 0, 0, 512);
    // hk = elu(ghid @ Whk + b_hk) (M=16384, fp32)
    gemm_mma<128,1,0,false,false><<<dim3(4,128,1), 256, SMEM_BYTES>>>(
        gh_hi, gh_lo, nullptr, nullptr, WTH(6), WTL(6), nb, nb, nb, nb,
        hk, nullptr, nullptr, nbm, nbm, b_hk, 16384, 512, 0, 0, 0, 512);
    build_hq<<<128, 256>>>((const float4*)dh, (const float4*)hh,
                           (const float4*)b_hq, (float4*)hq);
    final_kernel<<<256, 256>>>(hq, hk, attn, head, (float*)d_out);
}

// round 8
// speedup vs baseline: 1.6580x; 1.6580x over previous
#include <cuda_runtime.h>
#include <cuda_bf16.h>
#include <math.h>
#include <float.h>
#include <stdint.h>

// Problem dims: B=8, S=32, HN=64, TN=512, HID=EMB=512
// ---------------- scratch (device globals; no allocation) ----------------
__device__ float g_dh  [256 * 1024];            // [.,0:512)=decp  [.,512:1024)=hqd
__device__ float g_hh  [8   * 1024];            // [.,0:512)=histp [.,512:1024)=hqh
__device__ float g_headq[512  * 512];
__device__ float g_attn [8LL*2048*512];
__device__ float g_hk   [16384LL*512];
__device__ float g_hq   [256 * 512];
__device__ __nv_bfloat16 g_tq_hi [8LL*2048*512], g_tq_lo [8LL*2048*512];
__device__ __nv_bfloat16 g_tk_hi [4096LL*512],   g_tk_lo [4096LL*512];
__device__ __nv_bfloat16 g_tkT_hi[4096LL*512],   g_tkT_lo[4096LL*512];
__device__ __nv_bfloat16 g_at_hi [8LL*2048*512], g_at_lo [8LL*2048*512];
__device__ __nv_bfloat16 g_ctx_hi[8LL*2048*512], g_ctx_lo[8LL*2048*512];
__device__ __nv_bfloat16 g_gh_hi [8LL*2048*512], g_gh_lo [8LL*2048*512];
__device__ __nv_bfloat16 g_wT_hi [9LL*512*512],  g_wT_lo [9LL*512*512];
__device__ unsigned int g_mask_byte_mode;

__device__ __forceinline__ uint32_t smem_u32(const void* p) {
    uint32_t a;
    asm("{ .reg .u64 t; cvta.to.shared.u64 t, %1; cvt.u32.u64 %0, t; }" : "=r"(a) : "l"(p));
    return a;
}
__device__ __forceinline__ void cp16(uint32_t dst, const void* src) {
    asm volatile("cp.async.cg.shared.global [%0], [%1], 16;" :: "r"(dst), "l"(src));
}
__device__ __forceinline__ void mma_bf16(float* d, const uint32_t* a, const uint32_t* b) {
    asm volatile("mma.sync.aligned.m16n8k16.row.col.f32.bf16.bf16.f32 "
        "{%0,%1,%2,%3}, {%4,%5,%6,%7}, {%8,%9}, {%0,%1,%2,%3};"
        : "+f"(d[0]), "+f"(d[1]), "+f"(d[2]), "+f"(d[3])
        : "r"(a[0]), "r"(a[1]), "r"(a[2]), "r"(a[3]), "r"(b[0]), "r"(b[1]));
}
__device__ __forceinline__ void ldm_x4(uint32_t& r0, uint32_t& r1, uint32_t& r2, uint32_t& r3,
                                       uint32_t addr) {
    asm volatile("ldmatrix.sync.aligned.m8n8.x4.shared.b16 {%0,%1,%2,%3}, [%4];"
        : "=r"(r0), "=r"(r1), "=r"(r2), "=r"(r3) : "r"(addr));
}
__device__ __forceinline__ float eluf(float x) { return x > 0.f ? x : expm1f(x); }

// smem: NSTAGE buffers; each = A tile (64 rows x 144B) + B tile (128 x 144B)
// row layout: bytes [0,64) = hi 32 bf16, [64,128) = lo 32 bf16, [128,144) pad
#define ROWB   144
#define MT     64
#define ATILEB (MT * ROWB)           // 9216
#define BTILEB (128 * ROWB)          // 18432
#define BUFB   (ATILEB + BTILEB)     // 27648
#define NSTAGE 3
#define SMEM_BYTES (NSTAGE * BUFB)   // 82944 -> 2 CTAs/SM (165888 < 228K)

// ==================================================================
// bf16-split GEMM via mma.sync + ldmatrix, 3-stage cp.async pipeline, MT=64
// C[M, Ngrid] = act(A[M,K] @ B[Ngrid,K]^T (+pair2) + bias), ldc = C row stride
// ASRC: 0 = A pre-split bf16 hi/lo; 1 = gather fp32 rows of Af by gidx; 2 = fp32 rows
// TWO:  accumulate second (A2,B2) pair (same K)
// OUTB: write bf16 hi/lo, else fp32.  ACT: 0 none, 1 elu, 2 tanh
// ==================================================================
template<int ACT, int ASRC, bool TWO, bool OUTB>
__global__ void __launch_bounds__(256, 2) gemm_mma(
    const __nv_bfloat16* __restrict__ Ahi, const __nv_bfloat16* __restrict__ Alo,
    const float* __restrict__ Af, const int* __restrict__ gidx,
    const __nv_bfloat16* __restrict__ Bhi, const __nv_bfloat16* __restrict__ Blo,
    const __nv_bfloat16* __restrict__ A2hi, const __nv_bfloat16* __restrict__ A2lo,
    const __nv_bfloat16* __restrict__ B2hi, const __nv_bfloat16* __restrict__ B2lo,
    float* __restrict__ Cf, __nv_bfloat16* __restrict__ Chi, __nv_bfloat16* __restrict__ Clo,
    const float* __restrict__ bias,
    int M, int K, long long sA, long long sB, long long sC, int ldc)
{
    constexpr int FM = MT / 32;                     // 2 frag rows per warp
    extern __shared__ char sm[];
    const uint32_t smb = smem_u32(sm);
    const int tid = threadIdx.x, wid = tid >> 5, lane = tid & 31;
    const int wm = wid >> 2, wn = wid & 3;          // warp grid 2 (m) x 4 (n)
    const int m0 = blockIdx.y * MT, n0 = blockIdx.x * 128, z = blockIdx.z;

    const int kc  = K >> 5;                         // chunks of 32 fp32-k
    const int nch = TWO ? 2 * kc : kc;

    float d[FM][4][4];
    #pragma unroll
    for (int f = 0; f < FM; f++)
        #pragma unroll
        for (int g = 0; g < 4; g++)
            #pragma unroll
            for (int e = 0; e < 4; e++) d[f][g][e] = 0.f;

    auto load_chunk = [&](int c) {
        const bool sec = TWO && (c >= kc);
        const int koff = (sec ? c - kc : c) << 5;   // fp32-k offset
        const int buf = c % NSTAGE;
        const uint32_t smA = smb + buf * BUFB;
        const uint32_t smB = smA + ATILEB;
        char* smAp = sm + buf * BUFB;

        // ---- A (MT=64 rows) ----
        if constexpr (ASRC == 0) {
            const __nv_bfloat16* pH = (sec ? A2hi : Ahi) + (long long)z * sA;
            const __nv_bfloat16* pL = (sec ? A2lo : Alo) + (long long)z * sA;
            const int r = tid >> 2, s = tid & 3;    // 256 slots = 64 rows x 4 segs
            const long long go = (long long)(m0 + r) * K + koff + s * 8;
            const uint32_t dh = smA + r * ROWB + s * 16;
            cp16(dh,      pH + go);
            cp16(dh + 64, pL + go);
        } else {
            #pragma unroll
            for (int i = 0; i < 2; i++) {
                const int idx = tid + 256 * i;      // 0..511 = 64 rows x 8 float4
                const int r = idx >> 3, s = idx & 7;
                const int gm = m0 + r;
                float4 v = make_float4(0.f, 0.f, 0.f, 0.f);
                if (gm < M) {
                    const long long row = (ASRC == 1) ? (long long)gidx[gm] : (long long)gm;
                    v = *reinterpret_cast<const float4*>(Af + row * K + koff + s * 4);
                }
                __nv_bfloat162 h01 = __floats2bfloat162_rn(v.x, v.y);
                __nv_bfloat162 h23 = __floats2bfloat162_rn(v.z, v.w);
                float2 f01 = __bfloat1622float2(h01), f23 = __bfloat1622float2(h23);
                __nv_bfloat162 l01 = __floats2bfloat162_rn(v.x - f01.x, v.y - f01.y);
                __nv_bfloat162 l23 = __floats2bfloat162_rn(v.z - f23.x, v.w - f23.y);
                uint2 uh, ul;
                uh.x = *(uint32_t*)&h01; uh.y = *(uint32_t*)&h23;
                ul.x = *(uint32_t*)&l01; ul.y = *(uint32_t*)&l23;
                *reinterpret_cast<uint2*>(smAp + r * ROWB + s * 8)      = uh;
                *reinterpret_cast<uint2*>(smAp + r * ROWB + 64 + s * 8) = ul;
            }
        }
        // ---- B (always 128 rows, pre-split bf16) ----
        {
            const __nv_bfloat16* pH = (sec ? B2hi : Bhi) + (long long)z * sB;
            const __nv_bfloat16* pL = (sec ? B2lo : Blo) + (long long)z * sB;
            #pragma unroll
            for (int i = 0; i < 2; i++) {
                const int idx = tid + 256 * i;      // 0..511 = 128 rows x 4 segs
                const int r = idx >> 2, s = idx & 3;
                const long long go = (long long)(n0 + r) * K + koff + s * 8;
                const uint32_t dh = smB + r * ROWB + s * 16;
                cp16(dh,      pH + go);
                cp16(dh + 64, pL + go);
            }
        }
        asm volatile("cp.async.commit_group;");
    };

    load_chunk(0);
    if (nch > 1) load_chunk(1);

    // bf16-col offsets for the 6 k16 steps: AhBh, AhBl, AlBh
    const int stepA[6] = {0, 16, 0, 16, 32, 48};
    const int stepB[6] = {0, 16, 32, 48, 0, 16};

    // ldmatrix lane mapping (non-trans x4, matrices in lane-octet order)
    const int lrow = lane & 7, lsel = lane >> 3;
    const int a_dm = (lsel & 1) << 3, a_dk = (lsel >> 1) << 3;
    const int b_dn = (lsel >> 1) << 3, b_dk = (lsel & 1) << 3;

    for (int c = 0; c < nch; ++c) {
        if (c + 2 < nch) load_chunk(c + 2);
        const int rem = nch - 1 - c;
        if (rem >= 2)      asm volatile("cp.async.wait_group 2;");
        else if (rem == 1) asm volatile("cp.async.wait_group 1;");
        else               asm volatile("cp.async.wait_group 0;");
        __syncthreads();

        const uint32_t a_base = smb + (c % NSTAGE) * BUFB;
        const uint32_t b_base = a_base + ATILEB;

        #pragma unroll
        for (int st = 0; st < 6; ++st) {
            const int ka = stepA[st], kb = stepB[st];
            uint32_t a[FM][4], b[4][2];
            #pragma unroll
            for (int f = 0; f < FM; f++) {
                const uint32_t addr = a_base
                    + (uint32_t)((wm * 32 + f * 16 + a_dm + lrow) * ROWB + (ka + a_dk) * 2);
                ldm_x4(a[f][0], a[f][1], a[f][2], a[f][3], addr);
            }
            #pragma unroll
            for (int gp = 0; gp < 2; gp++) {
                const uint32_t addr = b_base
                    + (uint32_t)((wn * 32 + gp * 16 + b_dn + lrow) * ROWB + (kb + b_dk) * 2);
                ldm_x4(b[2*gp][0], b[2*gp][1], b[2*gp+1][0], b[2*gp+1][1], addr);
            }
            #pragma unroll
            for (int f = 0; f < FM; f++)
                #pragma unroll
                for (int g = 0; g < 4; g++)
                    mma_bf16(d[f][g], a[f], b[g]);
        }
        __syncthreads();
    }

    // ---- epilogue: fragments -> gmem with fused bias/act (+bf16 split) ----
    const int qr = lane >> 2, qc = 2 * (lane & 3);
    #pragma unroll
    for (int f = 0; f < FM; f++) {
        #pragma unroll
        for (int g = 0; g < 4; g++) {
            const int cc = n0 + wn * 32 + g * 8 + qc;
            float bx = 0.f, by = 0.f;
            if (bias) { bx = bias[cc]; by = bias[cc + 1]; }
            #pragma unroll
            for (int h = 0; h < 2; h++) {
                const int row = m0 + wm * 32 + f * 16 + qr + h * 8;
                if (row >= M) continue;
                float v0 = d[f][g][2 * h]     + bx;
                float v1 = d[f][g][2 * h + 1] + by;
                if (ACT == 1) { v0 = eluf(v0); v1 = eluf(v1); }
                else if (ACT == 2) { v0 = tanhf(v0); v1 = tanhf(v1); }
                const long long o = (long long)z * sC + (long long)row * ldc + cc;
                if constexpr (!OUTB) {
                    *reinterpret_cast<float2*>(Cf + o) = make_float2(v0, v1);
                } else {
                    __nv_bfloat162 hb = __floats2bfloat162_rn(v0, v1);
                    float2 hf = __bfloat1622float2(hb);
                    __nv_bfloat162 lb = __floats2bfloat162_rn(v0 - hf.x, v1 - hf.y);
                    *reinterpret_cast<__nv_bfloat162*>(Chi + o) = hb;
                    *reinterpret_cast<__nv_bfloat162*>(Clo + o) = lb;
                }
            }
        }
    }
}

// ---------------- weights: transpose 512x512 fp32 -> bf16 hi/lo ----------------
struct WPtrs { const float* s[9]; };
__global__ void prep_weights(WPtrs wp, __nv_bfloat16* __restrict__ dhi, __nv_bfloat16* __restrict__ dlo)
{
    __shared__ float t[32][33];
    const int mtx = blockIdx.z;
    const float* src = wp.s[mtx];
    __nv_bfloat16* oh = dhi + (long long)mtx * 512 * 512;
    __nv_bfloat16* ol = dlo + (long long)mtx * 512 * 512;
    const int tx = threadIdx.x, ty = threadIdx.y;
    const int bx = blockIdx.x * 32, by = blockIdx.y * 32;
    #pragma unroll
    for (int i = 0; i < 32; i += 8)
        t[ty + i][tx] = src[(long long)(by + ty + i) * 512 + bx + tx];
    __syncthreads();
    #pragma unroll
    for (int i = 0; i < 32; i += 8) {
        const float v = t[tx][ty + i];
        const __nv_bfloat16 h = __float2bfloat16(v);
        const long long o = (long long)(bx + ty + i) * 512 + by + tx;
        oh[o] = h;
        ol[o] = __float2bfloat16(v - __bfloat162float(h));
    }
}

// ---------------- history small GEMM: out[8][1024] = hist @ [Wh | Whq1] ----------------
__global__ void hist_small(const float* __restrict__ hist,
                           const __nv_bfloat16* __restrict__ w7h, const __nv_bfloat16* __restrict__ w7l,
                           const __nv_bfloat16* __restrict__ w8h, const __nv_bfloat16* __restrict__ w8l,
                           float* __restrict__ out)
{
    const int wid = threadIdx.x >> 5, lane = threadIdx.x & 31;
    const int c = blockIdx.x * 8 + wid;             // 0..1023
    const __nv_bfloat16* rh = (c < 512) ? w7h + (long long)c * 512 : w8h + (long long)(c - 512) * 512;
    const __nv_bfloat16* rl = (c < 512) ? w7l + (long long)c * 512 : w8l + (long long)(c - 512) * 512;
    float acc[8] = {0.f,0.f,0.f,0.f,0.f,0.f,0.f,0.f};
    #pragma unroll 4
    for (int i = 0; i < 16; i++) {
        const int k = lane + i * 32;
        const float w = __bfloat162float(rh[k]) + __bfloat162float(rl[k]);
        #pragma unroll
        for (int r = 0; r < 8; r++) acc[r] = fmaf(hist[r * 512 + k], w, acc[r]);
    }
    #pragma unroll
    for (int r = 0; r < 8; r++) {
        float v = acc[r];
        #pragma unroll
        for (int o = 16; o; o >>= 1) v += __shfl_xor_sync(0xffffffffu, v, o);
        if (lane == 0) out[r * 1024 + c] = v;
    }
}

// ---------------- tk transpose per batch (bf16 hi/lo) ----------------
__global__ void transpose_tk(const __nv_bfloat16* __restrict__ shi, const __nv_bfloat16* __restrict__ slo,
                             __nv_bfloat16* __restrict__ dhi, __nv_bfloat16* __restrict__ dlo)
{
    __shared__ __nv_bfloat16 th[32][33], tl[32][33];
    const long long zb = (long long)blockIdx.z * 512 * 512;
    const int tx = threadIdx.x, ty = threadIdx.y;
    const int bx = blockIdx.x * 32, by = blockIdx.y * 32;
    #pragma unroll
    for (int i = 0; i < 32; i += 8) {
        const long long o = zb + (long long)(by + ty + i) * 512 + bx + tx;
        th[ty + i][tx] = shi[o];
        tl[ty + i][tx] = slo[o];
    }
    __syncthreads();
    #pragma unroll
    for (int i = 0; i < 32; i += 8) {
        const long long o = zb + (long long)(bx + ty + i) * 512 + by + tx;
        dhi[o] = th[tx][ty + i];
        dlo[o] = tl[tx][ty + i];
    }
}

// ---------------- mask dtype detector ----------------
__global__ void detect_mask_kernel(const unsigned int* __restrict__ adj, int nwords)
{
    __shared__ unsigned int s;
    if (threadIdx.x == 0) s = 0u;
    __syncthreads();
    unsigned int local = 0u;
    for (int i = threadIdx.x; i < nwords; i += blockDim.x)
        local |= (adj[i] > 1u) ? 1u : 0u;
    if (local) atomicOr(&s, 1u);
    __syncthreads();
    if (threadIdx.x == 0) g_mask_byte_mode = s;
}

// ---------------- tq = elu(decp + histp + headq + b_tq) -> bf16 hi/lo ----------------
__global__ void build_tq(const float4* __restrict__ dh, const float4* __restrict__ hh,
                         const float4* __restrict__ headq, const float4* __restrict__ btq,
                         __nv_bfloat162* __restrict__ thi, __nv_bfloat162* __restrict__ tlo)
{
    const int i = blockIdx.x * 256 + threadIdx.x;
    const int d  = i & 127;
    const int h  = (i >> 7) & 63;
    const int bs = i >> 13;
    const int b  = bs >> 5;
    float4 a = dh[bs * 256 + d];
    float4 c = hh[b * 256 + d];
    float4 e = headq[(b * 64 + h) * 128 + d];
    float4 g = btq[d];
    float4 r;
    r.x = eluf(a.x + c.x + e.x + g.x);
    r.y = eluf(a.y + c.y + e.y + g.y);
    r.z = eluf(a.z + c.z + e.z + g.z);
    r.w = eluf(a.w + c.w + e.w + g.w);
    __nv_bfloat162 h0 = __floats2bfloat162_rn(r.x, r.y);
    __nv_bfloat162 h1 = __floats2bfloat162_rn(r.z, r.w);
    float2 f0 = __bfloat1622float2(h0), f1 = __bfloat1622float2(h1);
    __nv_bfloat162 l0 = __floats2bfloat162_rn(r.x - f0.x, r.y - f0.y);
    __nv_bfloat162 l1 = __floats2bfloat162_rn(r.z - f1.x, r.w - f1.y);
    thi[2 * i] = h0; thi[2 * i + 1] = h1;
    tlo[2 * i] = l0; tlo[2 * i + 1] = l1;
}

// ---------------- hq = elu(hqd + hqh + b_hq) (cols 512:1024) ----------------
__global__ void build_hq(const float4* __restrict__ dh, const float4* __restrict__ hh,
                         const float4* __restrict__ bhq, float4* __restrict__ hq)
{
    const int i = blockIdx.x * 256 + threadIdx.x;   // 0..32767
    const int d  = i & 127;
    const int bs = i >> 7;
    const int b  = bs >> 5;
    float4 a = dh[bs * 256 + 128 + d];
    float4 c = hh[b * 256 + 128 + d];
    float4 g = bhq[d];
    float4 r;
    r.x = eluf(a.x + c.x + g.x);
    r.y = eluf(a.y + c.y + g.y);
    r.z = eluf(a.z + c.z + g.z);
    r.w = eluf(a.w + c.w + g.w);
    hq[i] = r;
}

// ---------------- masked softmax (fp32 in place + bf16 hi/lo out) ----------------
__global__ void masked_softmax(float* __restrict__ attn,
                               __nv_bfloat16* __restrict__ ahi, __nv_bfloat16* __restrict__ alo,
                               const void* __restrict__ adj, const void* __restrict__ dup)
{
    const int q = blockIdx.x;
    const int b = blockIdx.y;
    const int s = q >> 6, h = q & 63;
    const long long ro = ((long long)(b * 2048 + q)) * 512;
    float* row = attn + ro;
    const long long aoff = ((long long)(b * 64 + h)) * 512;
    const long long doff = ((long long)(b * 32 + s)) * 512;

    const unsigned int byte_mode = g_mask_byte_mode;
    const unsigned char* am8 = (const unsigned char*)adj + aoff;
    const unsigned char* dm8 = (const unsigned char*)dup + doff;
    const int* am32 = (const int*)adj + aoff;
    const int* dm32 = (const int*)dup + doff;

    const int tid = threadIdx.x;
    float v[2]; int mk[2];
    float lmax = -FLT_MAX;
    #pragma unroll
    for (int j = 0; j < 2; j++) {
        const int t = tid + j * 256;
        if (byte_mode) mk[j] = am8[t]  && !dm8[t];
        else           mk[j] = am32[t] && !dm32[t];
        v[j] = row[t];
        if (mk[j]) lmax = fmaxf(lmax, v[j]);
    }
    __shared__ float smax[8], ssum[8];
    #pragma unroll
    for (int o = 16; o; o >>= 1) lmax = fmaxf(lmax, __shfl_xor_sync(0xffffffffu, lmax, o));
    if ((tid & 31) == 0) smax[tid >> 5] = lmax;
    __syncthreads();
    float bmax = -FLT_MAX;
    #pragma unroll
    for (int w = 0; w < 8; w++) bmax = fmaxf(bmax, smax[w]);

    float e[2], lsum = 0.f;
    #pragma unroll
    for (int j = 0; j < 2; j++) { e[j] = mk[j] ? expf(v[j] - bmax) : 0.f; lsum += e[j]; }
    #pragma unroll
    for (int o = 16; o; o >>= 1) lsum += __shfl_xor_sync(0xffffffffu, lsum, o);
    if ((tid & 31) == 0) ssum[tid >> 5] = lsum;
    __syncthreads();
    float bsum = 0.f;
    #pragma unroll
    for (int w = 0; w < 8; w++) bsum += ssum[w];

    const float inv = 1.f / bsum;
    #pragma unroll
    for (int j = 0; j < 2; j++) {
        const int t = tid + j * 256;
        const float p = e[j] * inv;
        row[t] = p;
        const __nv_bfloat16 hb = __float2bfloat16(p);
        ahi[ro + t] = hb;
        alo[ro + t] = __float2bfloat16(p - __bfloat162float(hb));
    }
}

// ---------------- final: head attention + prob + log ----------------
__global__ void final_kernel(const float* __restrict__ hq, const float* __restrict__ hk,
                             const float* __restrict__ attn, const int* __restrict__ head,
                             float* __restrict__ out)
{
    const int n = blockIdx.x;
    const int b = n >> 5;
    const int tid = threadIdx.x;

    __shared__ float shq[512];
    __shared__ float sc[64];
    __shared__ float sw[64];
    __shared__ int   s_len;

    if (tid == 0) s_len = 0;
    shq[tid]       = hq[(long long)n * 512 + tid];
    shq[tid + 256] = hq[(long long)n * 512 + 256 + tid];
    __syncthreads();
    if (tid < 64) { if (head[b * 64 + tid] != 0) atomicAdd(&s_len, 1); }
    __syncthreads();

    const int w = tid >> 5, lane = tid & 31;
    for (int k = w; k < 64; k += 8) {
        const float* hkr = hk + ((long long)n * 64 + k) * 512;
        float sacc = 0.f;
        for (int d = lane; d < 512; d += 32) sacc = fmaf(shq[d], hkr[d], sacc);
        #pragma unroll
        for (int o = 16; o; o >>= 1) sacc += __shfl_xor_sync(0xffffffffu, sacc, o);
        if (lane == 0) sc[k] = sacc;
    }
    __syncthreads();

    if (tid == 0) {
        const int len = s_len;
        float mx = -FLT_MAX;
        for (int k = 0; k < len; k++) mx = fmaxf(mx, sc[k]);
        float sum = 0.f;
        for (int k = 0; k < 64; k++) {
            float e = (k < len) ? expf(sc[k] - mx) : 0.f;
            sw[k] = e; sum += e;
        }
        float inv = 1.f / sum;
        for (int k = 0; k < 64; k++) sw[k] *= inv;
    }
    __syncthreads();

    const float* at = attn + (long long)n * 64 * 512;
    for (int t = tid; t < 512; t += 256) {
        float p = 0.f;
        #pragma unroll 8
        for (int k = 0; k < 64; k++) p = fmaf(sw[k], at[k * 512 + t], p);
        out[(long long)n * 512 + t] = logf(p + 1e-20f);
    }
}

// ---------------- launch ----------------
extern "C" void kernel_launch(void* const* d_in, const int* in_sizes, int n_in,
                              void* d_out, int out_size)
{
    const float* dec_out = (const float*)d_in[0];
    const float* history = (const float*)d_in[1];
    const int*   head    = (const int*)  d_in[2];
    const int*   tail    = (const int*)  d_in[3];
    const void*  adj     = d_in[4];
    const void*  dup     = d_in[5];
    const float* emb     = (const float*)d_in[6];
    const float* W_tq    = (const float*)d_in[7];
    const float* b_tq    = (const float*)d_in[8];
    const float* W_tk    = (const float*)d_in[9];
    const float* b_tk    = (const float*)d_in[10];
    const float* W_tout  = (const float*)d_in[11];
    const float* W_hq    = (const float*)d_in[12];
    const float* b_hq    = (const float*)d_in[13];
    const float* W_hk    = (const float*)d_in[14];
    const float* b_hk    = (const float*)d_in[15];

    float *dh, *hh, *headq, *attn, *hk, *hq;
    __nv_bfloat16 *tq_hi, *tq_lo, *tk_hi, *tk_lo, *tkT_hi, *tkT_lo;
    __nv_bfloat16 *at_hi, *at_lo, *ctx_hi, *ctx_lo, *gh_hi, *gh_lo, *wT_hi, *wT_lo;
    cudaGetSymbolAddress((void**)&dh,     g_dh);
    cudaGetSymbolAddress((void**)&hh,     g_hh);
    cudaGetSymbolAddress((void**)&headq,  g_headq);
    cudaGetSymbolAddress((void**)&attn,   g_attn);
    cudaGetSymbolAddress((void**)&hk,     g_hk);
    cudaGetSymbolAddress((void**)&hq,     g_hq);
    cudaGetSymbolAddress((void**)&tq_hi,  g_tq_hi);  cudaGetSymbolAddress((void**)&tq_lo,  g_tq_lo);
    cudaGetSymbolAddress((void**)&tk_hi,  g_tk_hi);  cudaGetSymbolAddress((void**)&tk_lo,  g_tk_lo);
    cudaGetSymbolAddress((void**)&tkT_hi, g_tkT_hi); cudaGetSymbolAddress((void**)&tkT_lo, g_tkT_lo);
    cudaGetSymbolAddress((void**)&at_hi,  g_at_hi);  cudaGetSymbolAddress((void**)&at_lo,  g_at_lo);
    cudaGetSymbolAddress((void**)&ctx_hi, g_ctx_hi); cudaGetSymbolAddress((void**)&ctx_lo, g_ctx_lo);
    cudaGetSymbolAddress((void**)&gh_hi,  g_gh_hi);  cudaGetSymbolAddress((void**)&gh_lo,  g_gh_lo);
    cudaGetSymbolAddress((void**)&wT_hi,  g_wT_hi);  cudaGetSymbolAddress((void**)&wT_lo,  g_wT_lo);

    cudaFuncSetAttribute(gemm_mma<0,2,false,false>, cudaFuncAttributeMaxDynamicSharedMemorySize, SMEM_BYTES);
    cudaFuncSetAttribute(gemm_mma<0,1,false,false>, cudaFuncAttributeMaxDynamicSharedMemorySize, SMEM_BYTES);
    cudaFuncSetAttribute(gemm_mma<1,1,false,true >, cudaFuncAttributeMaxDynamicSharedMemorySize, SMEM_BYTES);
    cudaFuncSetAttribute(gemm_mma<0,0,false,false>, cudaFuncAttributeMaxDynamicSharedMemorySize, SMEM_BYTES);
    cudaFuncSetAttribute(gemm_mma<0,0,false,true >, cudaFuncAttributeMaxDynamicSharedMemorySize, SMEM_BYTES);
    cudaFuncSetAttribute(gemm_mma<2,0,true ,true >, cudaFuncAttributeMaxDynamicSharedMemorySize, SMEM_BYTES);
    cudaFuncSetAttribute(gemm_mma<1,0,false,false>, cudaFuncAttributeMaxDynamicSharedMemorySize, SMEM_BYTES);

    // weight slots: 0 Wd, 1 Whq0 (merged N=1024), 2 We, 3 Wtk, 4 Wtout0, 5 Wtout1,
    //               6 Whk, 7 Wh, 8 Whq1 (7/8 consumed by hist_small)
    WPtrs wp;
    wp.s[0] = W_tq;               wp.s[1] = W_hq;               wp.s[2] = W_tq + 1024LL*512;
    wp.s[3] = W_tk;               wp.s[4] = W_tout;             wp.s[5] = W_tout + 512LL*512;
    wp.s[6] = W_hk;               wp.s[7] = W_tq + 512LL*512;   wp.s[8] = W_hq + 512LL*512;
    #define WTH(i) (wT_hi + (long long)(i)*512*512)
    #define WTL(i) (wT_lo + (long long)(i)*512*512)

    detect_mask_kernel<<<1, 256>>>((const unsigned int*)adj, 65536);
    prep_weights<<<dim3(16,16,9), dim3(32,8)>>>(wp, wT_hi, wT_lo);

    const __nv_bfloat16* nb = nullptr;

    // hh = history @ [Wh | Whq1]  (8 x 1024)
    hist_small<<<128, 256>>>(history, WTH(7), WTL(7), WTH(8), WTL(8), hh);
    // dh = dec_out @ [Wd | Whq0]  (256 x 1024)
    gemm_mma<0,2,false,false><<<dim3(8,4,1), 256, SMEM_BYTES>>>(
        nb, nb, dec_out, nullptr, WTH(0), WTL(0), nb, nb, nb, nb,
        dh, nullptr, nullptr, nullptr, 256, 512, 0, 0, 0, 1024);
    // headq = emb[head] @ We (M=512)
    gemm_mma<0,1,false,false><<<dim3(4,8,1), 256, SMEM_BYTES>>>(
        nb, nb, emb, head, WTH(2), WTL(2), nb, nb, nb, nb,
        headq, nullptr, nullptr, nullptr, 512, 512, 0, 0, 0, 512);
    // tk = elu(emb[tail] @ Wtk + b_tk) -> bf16 (M=4096)
    gemm_mma<1,1,false,true><<<dim3(4,64,1), 256, SMEM_BYTES>>>(
        nb, nb, emb, tail, WTH(3), WTL(3), nb, nb, nb, nb,
        nullptr, tk_hi, tk_lo, b_tk, 4096, 512, 0, 0, 0, 512);
    transpose_tk<<<dim3(16,16,8), dim3(32,8)>>>(tk_hi, tk_lo, tkT_hi, tkT_lo);
    build_tq<<<8192, 256>>>((const float4*)dh, (const float4*)hh,
                            (const float4*)headq, (const float4*)b_tq,
                            (__nv_bfloat162*)tq_hi, (__nv_bfloat162*)tq_lo);
    // scores[b] = tq[b] @ tk[b]^T  (M=2048 per batch)
    gemm_mma<0,0,false,false><<<dim3(4,32,8), 256, SMEM_BYTES>>>(
        tq_hi, tq_lo, nullptr, nullptr, tk_hi, tk_lo, nb, nb, nb, nb,
        attn, nullptr, nullptr, nullptr, 2048, 512,
        2048LL*512, 512LL*512, 2048LL*512, 512);
    masked_softmax<<<dim3(2048,8), 256>>>(attn, at_hi, at_lo, adj, dup);
    // ctx[b] = attn[b] @ tk[b] -> bf16
    gemm_mma<0,0,false,true><<<dim3(4,32,8), 256, SMEM_BYTES>>>(
        at_hi, at_lo, nullptr, nullptr, tkT_hi, tkT_lo, nb, nb, nb, nb,
        nullptr, ctx_hi, ctx_lo, nullptr, 2048, 512,
        2048LL*512, 512LL*512, 2048LL*512, 512);
    // ghid = tanh(ctx @ Wtout0 + tq @ Wtout1) -> bf16 (M=16384)
    gemm_mma<2,0,true,true><<<dim3(4,256,1), 256, SMEM_BYTES>>>(
        ctx_hi, ctx_lo, nullptr, nullptr, WTH(4), WTL(4),
        tq_hi, tq_lo, WTH(5), WTL(5),
        nullptr, gh_hi, gh_lo, nullptr, 16384, 512, 0, 0, 0, 512);
    // hk = elu(ghid @ Whk + b_hk) (M=16384, fp32)
    gemm_mma<1,0,false,false><<<dim3(4,256,1), 256, SMEM_BYTES>>>(
        gh_hi, gh_lo, nullptr, nullptr, WTH(6), WTL(6), nb, nb, nb, nb,
        hk, nullptr, nullptr, b_hk, 16384, 512, 0, 0, 0, 512);
    build_hq<<<128, 256>>>((const float4*)dh, (const float4*)hh,
                           (const float4*)b_hq, (float4*)hq);
    final_kernel<<<256, 256>>>(hq, hk, attn, head, (float*)d_out);
}

// round 9
// speedup vs baseline: 1.7203x; 1.0376x over previous
#include <cuda_runtime.h>
#include <cuda_bf16.h>
#include <math.h>
#include <float.h>
#include <stdint.h>

// Problem dims: B=8, S=32, HN=64, TN=512, HID=EMB=512
// ---------------- scratch (device globals; no allocation) ----------------
__device__ float g_dh  [256 * 1024];            // [.,0:512)=decp  [.,512:1024)=hqd
__device__ float g_hh  [8   * 1024];            // [.,0:512)=histp [.,512:1024)=hqh
__device__ float g_headq[512  * 512];
__device__ float g_attn [8LL*2048*512];
__device__ float g_hk   [16384LL*512];
__device__ float g_hq   [256 * 512];
__device__ __nv_bfloat16 g_tq_hi [8LL*2048*512], g_tq_lo [8LL*2048*512];
__device__ __nv_bfloat16 g_tk_hi [4096LL*512],   g_tk_lo [4096LL*512];
__device__ __nv_bfloat16 g_tkT_hi[4096LL*512],   g_tkT_lo[4096LL*512];
__device__ __nv_bfloat16 g_at_hi [8LL*2048*512], g_at_lo [8LL*2048*512];
__device__ __nv_bfloat16 g_ctx_hi[8LL*2048*512], g_ctx_lo[8LL*2048*512];
__device__ __nv_bfloat16 g_gh_hi [8LL*2048*512], g_gh_lo [8LL*2048*512];
__device__ __nv_bfloat16 g_wT_hi [9LL*512*512],  g_wT_lo [9LL*512*512];
__device__ unsigned int g_mask_byte_mode;

__device__ __forceinline__ uint32_t smem_u32(const void* p) {
    uint32_t a;
    asm("{ .reg .u64 t; cvta.to.shared.u64 t, %1; cvt.u32.u64 %0, t; }" : "=r"(a) : "l"(p));
    return a;
}
__device__ __forceinline__ void cp16(uint32_t dst, const void* src) {
    asm volatile("cp.async.cg.shared.global [%0], [%1], 16;" :: "r"(dst), "l"(src));
}
__device__ __forceinline__ void mma_bf16(float* d, const uint32_t* a, const uint32_t* b) {
    asm volatile("mma.sync.aligned.m16n8k16.row.col.f32.bf16.bf16.f32 "
        "{%0,%1,%2,%3}, {%4,%5,%6,%7}, {%8,%9}, {%0,%1,%2,%3};"
        : "+f"(d[0]), "+f"(d[1]), "+f"(d[2]), "+f"(d[3])
        : "r"(a[0]), "r"(a[1]), "r"(a[2]), "r"(a[3]), "r"(b[0]), "r"(b[1]));
}
__device__ __forceinline__ void ldm_x4(uint32_t& r0, uint32_t& r1, uint32_t& r2, uint32_t& r3,
                                       uint32_t addr) {
    asm volatile("ldmatrix.sync.aligned.m8n8.x4.shared.b16 {%0,%1,%2,%3}, [%4];"
        : "=r"(r0), "=r"(r1), "=r"(r2), "=r"(r3) : "r"(addr));
}
__device__ __forceinline__ float eluf(float x) { return x > 0.f ? x : expm1f(x); }

// smem: NSTAGE buffers; each = A tile (64 rows x 144B) + B tile (128 x 144B)
// row layout: bytes [0,64) = hi 32 bf16, [64,128) = lo 32 bf16, [128,144) pad
#define ROWB   144
#define MT     64
#define ATILEB (MT * ROWB)           // 9216
#define BTILEB (128 * ROWB)          // 18432
#define BUFB   (ATILEB + BTILEB)     // 27648
#define NSTAGE 4
#define SMEM_BYTES (NSTAGE * BUFB)   // 110592 -> 2 CTAs/SM (221184 <= 228K)

// ldmatrix lane-mapping helpers
#define LDM_SETUP \
    const int lrow = lane & 7, lsel = lane >> 3; \
    const int a_dm = (lsel & 1) << 3, a_dk = (lsel >> 1) << 3; \
    const int b_dn = (lsel >> 1) << 3, b_dk = (lsel & 1) << 3;

__device__ __forceinline__ void pipe_wait(int rem) {
    if (rem >= 3)      asm volatile("cp.async.wait_group 3;");
    else if (rem == 2) asm volatile("cp.async.wait_group 2;");
    else if (rem == 1) asm volatile("cp.async.wait_group 1;");
    else               asm volatile("cp.async.wait_group 0;");
}

// ==================================================================
// Main bf16-split GEMM (pre-split bf16 A), 4-stage pipeline, MT=64
// ==================================================================
template<int ACT, bool TWO, bool OUTB>
__global__ void __launch_bounds__(256, 2) gemm_mma(
    const __nv_bfloat16* __restrict__ Ahi, const __nv_bfloat16* __restrict__ Alo,
    const __nv_bfloat16* __restrict__ Bhi, const __nv_bfloat16* __restrict__ Blo,
    const __nv_bfloat16* __restrict__ A2hi, const __nv_bfloat16* __restrict__ A2lo,
    const __nv_bfloat16* __restrict__ B2hi, const __nv_bfloat16* __restrict__ B2lo,
    float* __restrict__ Cf, __nv_bfloat16* __restrict__ Chi, __nv_bfloat16* __restrict__ Clo,
    const float* __restrict__ bias,
    int M, int K, long long sA, long long sB, long long sC, int ldc)
{
    constexpr int FM = 2;
    extern __shared__ char sm[];
    const uint32_t smb = smem_u32(sm);
    const int tid = threadIdx.x, wid = tid >> 5, lane = tid & 31;
    const int wm = wid >> 2, wn = wid & 3;
    const int m0 = blockIdx.y * MT, n0 = blockIdx.x * 128, z = blockIdx.z;

    const int kc  = K >> 5;
    const int nch = TWO ? 2 * kc : kc;

    float d[FM][4][4];
    #pragma unroll
    for (int f = 0; f < FM; f++)
        #pragma unroll
        for (int g = 0; g < 4; g++)
            #pragma unroll
            for (int e = 0; e < 4; e++) d[f][g][e] = 0.f;

    auto load_chunk = [&](int c) {
        const bool sec = TWO && (c >= kc);
        const int koff = (sec ? c - kc : c) << 5;
        const int buf = c % NSTAGE;
        const uint32_t smA = smb + buf * BUFB;
        const uint32_t smB = smA + ATILEB;
        {
            const __nv_bfloat16* pH = (sec ? A2hi : Ahi) + (long long)z * sA;
            const __nv_bfloat16* pL = (sec ? A2lo : Alo) + (long long)z * sA;
            const int r = tid >> 2, s = tid & 3;
            const long long go = (long long)(m0 + r) * K + koff + s * 8;
            const uint32_t dst = smA + r * ROWB + s * 16;
            cp16(dst,      pH + go);
            cp16(dst + 64, pL + go);
        }
        {
            const __nv_bfloat16* pH = (sec ? B2hi : Bhi) + (long long)z * sB;
            const __nv_bfloat16* pL = (sec ? B2lo : Blo) + (long long)z * sB;
            #pragma unroll
            for (int i = 0; i < 2; i++) {
                const int idx = tid + 256 * i;
                const int r = idx >> 2, s = idx & 3;
                const long long go = (long long)(n0 + r) * K + koff + s * 8;
                const uint32_t dst = smB + r * ROWB + s * 16;
                cp16(dst,      pH + go);
                cp16(dst + 64, pL + go);
            }
        }
        asm volatile("cp.async.commit_group;");
    };

    #pragma unroll
    for (int p = 0; p < NSTAGE - 1; p++) if (p < nch) load_chunk(p);

    const int stepA[6] = {0, 16, 0, 16, 32, 48};
    const int stepB[6] = {0, 16, 32, 48, 0, 16};
    LDM_SETUP

    for (int c = 0; c < nch; ++c) {
        if (c + NSTAGE - 1 < nch) load_chunk(c + NSTAGE - 1);
        pipe_wait(nch - 1 - c);
        __syncthreads();

        const uint32_t a_base = smb + (c % NSTAGE) * BUFB;
        const uint32_t b_base = a_base + ATILEB;

        #pragma unroll
        for (int st = 0; st < 6; ++st) {
            const int ka = stepA[st], kb = stepB[st];
            uint32_t a[FM][4], b[4][2];
            #pragma unroll
            for (int f = 0; f < FM; f++) {
                const uint32_t addr = a_base
                    + (uint32_t)((wm * 32 + f * 16 + a_dm + lrow) * ROWB + (ka + a_dk) * 2);
                ldm_x4(a[f][0], a[f][1], a[f][2], a[f][3], addr);
            }
            #pragma unroll
            for (int gp = 0; gp < 2; gp++) {
                const uint32_t addr = b_base
                    + (uint32_t)((wn * 32 + gp * 16 + b_dn + lrow) * ROWB + (kb + b_dk) * 2);
                ldm_x4(b[2*gp][0], b[2*gp][1], b[2*gp+1][0], b[2*gp+1][1], addr);
            }
            #pragma unroll
            for (int f = 0; f < FM; f++)
                #pragma unroll
                for (int g = 0; g < 4; g++)
                    mma_bf16(d[f][g], a[f], b[g]);
        }
        __syncthreads();
    }

    const int qr = lane >> 2, qc = 2 * (lane & 3);
    #pragma unroll
    for (int f = 0; f < FM; f++) {
        #pragma unroll
        for (int g = 0; g < 4; g++) {
            const int cc = n0 + wn * 32 + g * 8 + qc;
            float bx = 0.f, by = 0.f;
            if (bias) { bx = bias[cc]; by = bias[cc + 1]; }
            #pragma unroll
            for (int h = 0; h < 2; h++) {
                const int row = m0 + wm * 32 + f * 16 + qr + h * 8;
                if (row >= M) continue;
                float v0 = d[f][g][2 * h]     + bx;
                float v1 = d[f][g][2 * h + 1] + by;
                if (ACT == 1) { v0 = eluf(v0); v1 = eluf(v1); }
                else if (ACT == 2) { v0 = tanhf(v0); v1 = tanhf(v1); }
                const long long o = (long long)z * sC + (long long)row * ldc + cc;
                if constexpr (!OUTB) {
                    *reinterpret_cast<float2*>(Cf + o) = make_float2(v0, v1);
                } else {
                    __nv_bfloat162 hb = __floats2bfloat162_rn(v0, v1);
                    float2 hf = __bfloat1622float2(hb);
                    __nv_bfloat162 lb = __floats2bfloat162_rn(v0 - hf.x, v1 - hf.y);
                    *reinterpret_cast<__nv_bfloat162*>(Chi + o) = hb;
                    *reinterpret_cast<__nv_bfloat162*>(Clo + o) = lb;
                }
            }
        }
    }
}

// ==================================================================
// Prologue uber-GEMM: one launch covers dh (256x1024), headq (512x512),
// tk (4096x512, elu, bf16-split out). A is fp32 (optional gather), K=512.
// Grid 320 CTAs: [0,32) dh, [32,64) headq, [64,320) tk
// ==================================================================
__global__ void __launch_bounds__(256, 2) gemm_pro(
    const float* __restrict__ dec_out, const float* __restrict__ emb,
    const int* __restrict__ head, const int* __restrict__ tail,
    const __nv_bfloat16* __restrict__ wT_hi, const __nv_bfloat16* __restrict__ wT_lo,
    float* __restrict__ dh, float* __restrict__ headq,
    __nv_bfloat16* __restrict__ tk_hi, __nv_bfloat16* __restrict__ tk_lo,
    const float* __restrict__ b_tk)
{
    constexpr int FM = 2;
    extern __shared__ char sm[];
    const uint32_t smb = smem_u32(sm);
    const int tid = threadIdx.x, wid = tid >> 5, lane = tid & 31;
    const int wm = wid >> 2, wn = wid & 3;

    // decode job
    const int bid = blockIdx.x;
    const float* Af; const int* gidx; long long boff; float* Cf; int ldc;
    int m0, n0; int outb, act; const float* bias;
    if (bid < 32) {            // dh: 8 n-tiles x 4 m-tiles, B = slots 0..1 (contig 1024 rows)
        Af = dec_out; gidx = nullptr; boff = 0;
        Cf = dh; ldc = 1024; outb = 0; act = 0; bias = nullptr;
        n0 = (bid & 7) * 128; m0 = (bid >> 3) * MT;
    } else if (bid < 64) {     // headq: 4 n x 8 m, B = slot 2
        const int t = bid - 32;
        Af = emb; gidx = head; boff = 2LL * 512 * 512;
        Cf = headq; ldc = 512; outb = 0; act = 0; bias = nullptr;
        n0 = (t & 3) * 128; m0 = (t >> 2) * MT;
    } else {                   // tk: 4 n x 64 m, B = slot 3
        const int t = bid - 64;
        Af = emb; gidx = tail; boff = 3LL * 512 * 512;
        Cf = nullptr; ldc = 512; outb = 1; act = 1; bias = b_tk;
        n0 = (t & 3) * 128; m0 = (t >> 2) * MT;
    }
    const __nv_bfloat16* Bhi = wT_hi + boff;
    const __nv_bfloat16* Blo = wT_lo + boff;
    const int K = 512, nch = 16;

    float d[FM][4][4];
    #pragma unroll
    for (int f = 0; f < FM; f++)
        #pragma unroll
        for (int g = 0; g < 4; g++)
            #pragma unroll
            for (int e = 0; e < 4; e++) d[f][g][e] = 0.f;

    auto load_chunk = [&](int c) {
        const int koff = c << 5;
        const int buf = c % NSTAGE;
        const uint32_t smA = smb + buf * BUFB;
        const uint32_t smB = smA + ATILEB;
        char* smAp = sm + buf * BUFB;
        // A: fp32 -> split bf16 (64 rows x 8 float4)
        #pragma unroll
        for (int i = 0; i < 2; i++) {
            const int idx = tid + 256 * i;
            const int r = idx >> 3, s = idx & 7;
            const int gm = m0 + r;
            const long long row = gidx ? (long long)gidx[gm] : (long long)gm;
            float4 v = *reinterpret_cast<const float4*>(Af + row * K + koff + s * 4);
            __nv_bfloat162 h01 = __floats2bfloat162_rn(v.x, v.y);
            __nv_bfloat162 h23 = __floats2bfloat162_rn(v.z, v.w);
            float2 f01 = __bfloat1622float2(h01), f23 = __bfloat1622float2(h23);
            __nv_bfloat162 l01 = __floats2bfloat162_rn(v.x - f01.x, v.y - f01.y);
            __nv_bfloat162 l23 = __floats2bfloat162_rn(v.z - f23.x, v.w - f23.y);
            uint2 uh, ul;
            uh.x = *(uint32_t*)&h01; uh.y = *(uint32_t*)&h23;
            ul.x = *(uint32_t*)&l01; ul.y = *(uint32_t*)&l23;
            *reinterpret_cast<uint2*>(smAp + r * ROWB + s * 8)      = uh;
            *reinterpret_cast<uint2*>(smAp + r * ROWB + 64 + s * 8) = ul;
        }
        // B
        #pragma unroll
        for (int i = 0; i < 2; i++) {
            const int idx = tid + 256 * i;
            const int r = idx >> 2, s = idx & 3;
            const long long go = (long long)(n0 + r) * K + koff + s * 8;
            const uint32_t dst = smB + r * ROWB + s * 16;
            cp16(dst,      Bhi + go);
            cp16(dst + 64, Blo + go);
        }
        asm volatile("cp.async.commit_group;");
    };

    #pragma unroll
    for (int p = 0; p < NSTAGE - 1; p++) load_chunk(p);

    const int stepA[6] = {0, 16, 0, 16, 32, 48};
    const int stepB[6] = {0, 16, 32, 48, 0, 16};
    LDM_SETUP

    for (int c = 0; c < nch; ++c) {
        if (c + NSTAGE - 1 < nch) load_chunk(c + NSTAGE - 1);
        pipe_wait(nch - 1 - c);
        __syncthreads();

        const uint32_t a_base = smb + (c % NSTAGE) * BUFB;
        const uint32_t b_base = a_base + ATILEB;

        #pragma unroll
        for (int st = 0; st < 6; ++st) {
            const int ka = stepA[st], kb = stepB[st];
            uint32_t a[FM][4], b[4][2];
            #pragma unroll
            for (int f = 0; f < FM; f++) {
                const uint32_t addr = a_base
                    + (uint32_t)((wm * 32 + f * 16 + a_dm + lrow) * ROWB + (ka + a_dk) * 2);
                ldm_x4(a[f][0], a[f][1], a[f][2], a[f][3], addr);
            }
            #pragma unroll
            for (int gp = 0; gp < 2; gp++) {
                const uint32_t addr = b_base
                    + (uint32_t)((wn * 32 + gp * 16 + b_dn + lrow) * ROWB + (kb + b_dk) * 2);
                ldm_x4(b[2*gp][0], b[2*gp][1], b[2*gp+1][0], b[2*gp+1][1], addr);
            }
            #pragma unroll
            for (int f = 0; f < FM; f++)
                #pragma unroll
                for (int g = 0; g < 4; g++)
                    mma_bf16(d[f][g], a[f], b[g]);
        }
        __syncthreads();
    }

    const int qr = lane >> 2, qc = 2 * (lane & 3);
    #pragma unroll
    for (int f = 0; f < FM; f++) {
        #pragma unroll
        for (int g = 0; g < 4; g++) {
            const int cc = n0 + wn * 32 + g * 8 + qc;
            float bx = 0.f, by = 0.f;
            if (bias) { bx = bias[cc]; by = bias[cc + 1]; }
            #pragma unroll
            for (int h = 0; h < 2; h++) {
                const int row = m0 + wm * 32 + f * 16 + qr + h * 8;
                float v0 = d[f][g][2 * h]     + bx;
                float v1 = d[f][g][2 * h + 1] + by;
                if (act == 1) { v0 = eluf(v0); v1 = eluf(v1); }
                if (!outb) {
                    *reinterpret_cast<float2*>(Cf + (long long)row * ldc + cc) = make_float2(v0, v1);
                } else {
                    __nv_bfloat162 hb = __floats2bfloat162_rn(v0, v1);
                    float2 hf = __bfloat1622float2(hb);
                    __nv_bfloat162 lb = __floats2bfloat162_rn(v0 - hf.x, v1 - hf.y);
                    const long long o = (long long)row * 512 + cc;
                    *reinterpret_cast<__nv_bfloat162*>(tk_hi + o) = hb;
                    *reinterpret_cast<__nv_bfloat162*>(tk_lo + o) = lb;
                }
            }
        }
    }
}

// ---------------- weights: transpose 512x512 fp32 -> bf16 hi/lo ----------------
struct WPtrs { const float* s[9]; };
__global__ void prep_weights(WPtrs wp, __nv_bfloat16* __restrict__ dhi, __nv_bfloat16* __restrict__ dlo)
{
    __shared__ float t[32][33];
    const int mtx = blockIdx.z;
    const float* src = wp.s[mtx];
    __nv_bfloat16* oh = dhi + (long long)mtx * 512 * 512;
    __nv_bfloat16* ol = dlo + (long long)mtx * 512 * 512;
    const int tx = threadIdx.x, ty = threadIdx.y;
    const int bx = blockIdx.x * 32, by = blockIdx.y * 32;
    #pragma unroll
    for (int i = 0; i < 32; i += 8)
        t[ty + i][tx] = src[(long long)(by + ty + i) * 512 + bx + tx];
    __syncthreads();
    #pragma unroll
    for (int i = 0; i < 32; i += 8) {
        const float v = t[tx][ty + i];
        const __nv_bfloat16 h = __float2bfloat16(v);
        const long long o = (long long)(bx + ty + i) * 512 + by + tx;
        oh[o] = h;
        ol[o] = __float2bfloat16(v - __bfloat162float(h));
    }
}

// ---------------- history small GEMM: out[8][1024] = hist @ [Wh | Whq1] ----------------
__global__ void hist_small(const float* __restrict__ hist,
                           const __nv_bfloat16* __restrict__ w7h, const __nv_bfloat16* __restrict__ w7l,
                           const __nv_bfloat16* __restrict__ w8h, const __nv_bfloat16* __restrict__ w8l,
                           float* __restrict__ out)
{
    const int wid = threadIdx.x >> 5, lane = threadIdx.x & 31;
    const int c = blockIdx.x * 8 + wid;             // 0..1023
    const __nv_bfloat16* rh = (c < 512) ? w7h + (long long)c * 512 : w8h + (long long)(c - 512) * 512;
    const __nv_bfloat16* rl = (c < 512) ? w7l + (long long)c * 512 : w8l + (long long)(c - 512) * 512;
    float acc[8] = {0.f,0.f,0.f,0.f,0.f,0.f,0.f,0.f};
    #pragma unroll 4
    for (int i = 0; i < 16; i++) {
        const int k = lane + i * 32;
        const float w = __bfloat162float(rh[k]) + __bfloat162float(rl[k]);
        #pragma unroll
        for (int r = 0; r < 8; r++) acc[r] = fmaf(hist[r * 512 + k], w, acc[r]);
    }
    #pragma unroll
    for (int r = 0; r < 8; r++) {
        float v = acc[r];
        #pragma unroll
        for (int o = 16; o; o >>= 1) v += __shfl_xor_sync(0xffffffffu, v, o);
        if (lane == 0) out[r * 1024 + c] = v;
    }
}

// ---------------- tk transpose per batch (bf16 hi/lo) ----------------
__global__ void transpose_tk(const __nv_bfloat16* __restrict__ shi, const __nv_bfloat16* __restrict__ slo,
                             __nv_bfloat16* __restrict__ dhi, __nv_bfloat16* __restrict__ dlo)
{
    __shared__ __nv_bfloat16 th[32][33], tl[32][33];
    const long long zb = (long long)blockIdx.z * 512 * 512;
    const int tx = threadIdx.x, ty = threadIdx.y;
    const int bx = blockIdx.x * 32, by = blockIdx.y * 32;
    #pragma unroll
    for (int i = 0; i < 32; i += 8) {
        const long long o = zb + (long long)(by + ty + i) * 512 + bx + tx;
        th[ty + i][tx] = shi[o];
        tl[ty + i][tx] = slo[o];
    }
    __syncthreads();
    #pragma unroll
    for (int i = 0; i < 32; i += 8) {
        const long long o = zb + (long long)(bx + ty + i) * 512 + by + tx;
        dhi[o] = th[tx][ty + i];
        dlo[o] = tl[tx][ty + i];
    }
}

// ---------------- mask dtype detector ----------------
__global__ void detect_mask_kernel(const unsigned int* __restrict__ adj, int nwords)
{
    __shared__ unsigned int s;
    if (threadIdx.x == 0) s = 0u;
    __syncthreads();
    unsigned int local = 0u;
    for (int i = threadIdx.x; i < nwords; i += blockDim.x)
        local |= (adj[i] > 1u) ? 1u : 0u;
    if (local) atomicOr(&s, 1u);
    __syncthreads();
    if (threadIdx.x == 0) g_mask_byte_mode = s;
}

// ---------------- tq = elu(decp + histp + headq + b_tq) -> bf16 hi/lo ----------------
__global__ void build_tq(const float4* __restrict__ dh, const float4* __restrict__ hh,
                         const float4* __restrict__ headq, const float4* __restrict__ btq,
                         __nv_bfloat162* __restrict__ thi, __nv_bfloat162* __restrict__ tlo)
{
    const int i = blockIdx.x * 256 + threadIdx.x;
    const int d  = i & 127;
    const int h  = (i >> 7) & 63;
    const int bs = i >> 13;
    const int b  = bs >> 5;
    float4 a = dh[bs * 256 + d];
    float4 c = hh[b * 256 + d];
    float4 e = headq[(b * 64 + h) * 128 + d];
    float4 g = btq[d];
    float4 r;
    r.x = eluf(a.x + c.x + e.x + g.x);
    r.y = eluf(a.y + c.y + e.y + g.y);
    r.z = eluf(a.z + c.z + e.z + g.z);
    r.w = eluf(a.w + c.w + e.w + g.w);
    __nv_bfloat162 h0 = __floats2bfloat162_rn(r.x, r.y);
    __nv_bfloat162 h1 = __floats2bfloat162_rn(r.z, r.w);
    float2 f0 = __bfloat1622float2(h0), f1 = __bfloat1622float2(h1);
    __nv_bfloat162 l0 = __floats2bfloat162_rn(r.x - f0.x, r.y - f0.y);
    __nv_bfloat162 l1 = __floats2bfloat162_rn(r.z - f1.x, r.w - f1.y);
    thi[2 * i] = h0; thi[2 * i + 1] = h1;
    tlo[2 * i] = l0; tlo[2 * i + 1] = l1;
}

// ---------------- hq = elu(hqd + hqh + b_hq) (cols 512:1024) ----------------
__global__ void build_hq(const float4* __restrict__ dh, const float4* __restrict__ hh,
                         const float4* __restrict__ bhq, float4* __restrict__ hq)
{
    const int i = blockIdx.x * 256 + threadIdx.x;   // 0..32767
    const int d  = i & 127;
    const int bs = i >> 7;
    const int b  = bs >> 5;
    float4 a = dh[bs * 256 + 128 + d];
    float4 c = hh[b * 256 + 128 + d];
    float4 g = bhq[d];
    float4 r;
    r.x = eluf(a.x + c.x + g.x);
    r.y = eluf(a.y + c.y + g.y);
    r.z = eluf(a.z + c.z + g.z);
    r.w = eluf(a.w + c.w + g.w);
    hq[i] = r;
}

// ---------------- masked softmax (fp32 in place + bf16 hi/lo out) ----------------
__global__ void masked_softmax(float* __restrict__ attn,
                               __nv_bfloat16* __restrict__ ahi, __nv_bfloat16* __restrict__ alo,
                               const void* __restrict__ adj, const void* __restrict__ dup)
{
    const int q = blockIdx.x;
    const int b = blockIdx.y;
    const int s = q >> 6, h = q & 63;
    const long long ro = ((long long)(b * 2048 + q)) * 512;
    float* row = attn + ro;
    const long long aoff = ((long long)(b * 64 + h)) * 512;
    const long long doff = ((long long)(b * 32 + s)) * 512;

    const unsigned int byte_mode = g_mask_byte_mode;
    const unsigned char* am8 = (const unsigned char*)adj + aoff;
    const unsigned char* dm8 = (const unsigned char*)dup + doff;
    const int* am32 = (const int*)adj + aoff;
    const int* dm32 = (const int*)dup + doff;

    const int tid = threadIdx.x;
    float v[2]; int mk[2];
    float lmax = -FLT_MAX;
    #pragma unroll
    for (int j = 0; j < 2; j++) {
        const int t = tid + j * 256;
        if (byte_mode) mk[j] = am8[t]  && !dm8[t];
        else           mk[j] = am32[t] && !dm32[t];
        v[j] = row[t];
        if (mk[j]) lmax = fmaxf(lmax, v[j]);
    }
    __shared__ float smax[8], ssum[8];
    #pragma unroll
    for (int o = 16; o; o >>= 1) lmax = fmaxf(lmax, __shfl_xor_sync(0xffffffffu, lmax, o));
    if ((tid & 31) == 0) smax[tid >> 5] = lmax;
    __syncthreads();
    float bmax = -FLT_MAX;
    #pragma unroll
    for (int w = 0; w < 8; w++) bmax = fmaxf(bmax, smax[w]);

    float e[2], lsum = 0.f;
    #pragma unroll
    for (int j = 0; j < 2; j++) { e[j] = mk[j] ? expf(v[j] - bmax) : 0.f; lsum += e[j]; }
    #pragma unroll
    for (int o = 16; o; o >>= 1) lsum += __shfl_xor_sync(0xffffffffu, lsum, o);
    if ((tid & 31) == 0) ssum[tid >> 5] = lsum;
    __syncthreads();
    float bsum = 0.f;
    #pragma unroll
    for (int w = 0; w < 8; w++) bsum += ssum[w];

    const float inv = 1.f / bsum;
    #pragma unroll
    for (int j = 0; j < 2; j++) {
        const int t = tid + j * 256;
        const float p = e[j] * inv;
        row[t] = p;
        const __nv_bfloat16 hb = __float2bfloat16(p);
        ahi[ro + t] = hb;
        alo[ro + t] = __float2bfloat16(p - __bfloat162float(hb));
    }
}

// ---------------- final: head attention + prob + log ----------------
__global__ void final_kernel(const float* __restrict__ hq, const float* __restrict__ hk,
                             const float* __restrict__ attn, const int* __restrict__ head,
                             float* __restrict__ out)
{
    const int n = blockIdx.x;
    const int b = n >> 5;
    const int tid = threadIdx.x;

    __shared__ float shq[512];
    __shared__ float sc[64];
    __shared__ float sw[64];
    __shared__ int   s_len;

    if (tid == 0) s_len = 0;
    shq[tid]       = hq[(long long)n * 512 + tid];
    shq[tid + 256] = hq[(long long)n * 512 + 256 + tid];
    __syncthreads();
    if (tid < 64) { if (head[b * 64 + tid] != 0) atomicAdd(&s_len, 1); }
    __syncthreads();

    const int w = tid >> 5, lane = tid & 31;
    for (int k = w; k < 64; k += 8) {
        const float* hkr = hk + ((long long)n * 64 + k) * 512;
        float sacc = 0.f;
        for (int d = lane; d < 512; d += 32) sacc = fmaf(shq[d], hkr[d], sacc);
        #pragma unroll
        for (int o = 16; o; o >>= 1) sacc += __shfl_xor_sync(0xffffffffu, sacc, o);
        if (lane == 0) sc[k] = sacc;
    }
    __syncthreads();

    if (tid == 0) {
        const int len = s_len;
        float mx = -FLT_MAX;
        for (int k = 0; k < len; k++) mx = fmaxf(mx, sc[k]);
        float sum = 0.f;
        for (int k = 0; k < 64; k++) {
            float e = (k < len) ? expf(sc[k] - mx) : 0.f;
            sw[k] = e; sum += e;
        }
        float inv = 1.f / sum;
        for (int k = 0; k < 64; k++) sw[k] *= inv;
    }
    __syncthreads();

    const float* at = attn + (long long)n * 64 * 512;
    for (int t = tid; t < 512; t += 256) {
        float p = 0.f;
        #pragma unroll 8
        for (int k = 0; k < 64; k++) p = fmaf(sw[k], at[k * 512 + t], p);
        out[(long long)n * 512 + t] = logf(p + 1e-20f);
    }
}

// ---------------- launch ----------------
extern "C" void kernel_launch(void* const* d_in, const int* in_sizes, int n_in,
                              void* d_out, int out_size)
{
    const float* dec_out = (const float*)d_in[0];
    const float* history = (const float*)d_in[1];
    const int*   head    = (const int*)  d_in[2];
    const int*   tail    = (const int*)  d_in[3];
    const void*  adj     = d_in[4];
    const void*  dup     = d_in[5];
    const float* emb     = (const float*)d_in[6];
    const float* W_tq    = (const float*)d_in[7];
    const float* b_tq    = (const float*)d_in[8];
    const float* W_tk    = (const float*)d_in[9];
    const float* b_tk    = (const float*)d_in[10];
    const float* W_tout  = (const float*)d_in[11];
    const float* W_hq    = (const float*)d_in[12];
    const float* b_hq    = (const float*)d_in[13];
    const float* W_hk    = (const float*)d_in[14];
    const float* b_hk    = (const float*)d_in[15];

    float *dh, *hh, *headq, *attn, *hk, *hq;
    __nv_bfloat16 *tq_hi, *tq_lo, *tk_hi, *tk_lo, *tkT_hi, *tkT_lo;
    __nv_bfloat16 *at_hi, *at_lo, *ctx_hi, *ctx_lo, *gh_hi, *gh_lo, *wT_hi, *wT_lo;
    cudaGetSymbolAddress((void**)&dh,     g_dh);
    cudaGetSymbolAddress((void**)&hh,     g_hh);
    cudaGetSymbolAddress((void**)&headq,  g_headq);
    cudaGetSymbolAddress((void**)&attn,   g_attn);
    cudaGetSymbolAddress((void**)&hk,     g_hk);
    cudaGetSymbolAddress((void**)&hq,     g_hq);
    cudaGetSymbolAddress((void**)&tq_hi,  g_tq_hi);  cudaGetSymbolAddress((void**)&tq_lo,  g_tq_lo);
    cudaGetSymbolAddress((void**)&tk_hi,  g_tk_hi);  cudaGetSymbolAddress((void**)&tk_lo,  g_tk_lo);
    cudaGetSymbolAddress((void**)&tkT_hi, g_tkT_hi); cudaGetSymbolAddress((void**)&tkT_lo, g_tkT_lo);
    cudaGetSymbolAddress((void**)&at_hi,  g_at_hi);  cudaGetSymbolAddress((void**)&at_lo,  g_at_lo);
    cudaGetSymbolAddress((void**)&ctx_hi, g_ctx_hi); cudaGetSymbolAddress((void**)&ctx_lo, g_ctx_lo);
    cudaGetSymbolAddress((void**)&gh_hi,  g_gh_hi);  cudaGetSymbolAddress((void**)&gh_lo,  g_gh_lo);
    cudaGetSymbolAddress((void**)&wT_hi,  g_wT_hi);  cudaGetSymbolAddress((void**)&wT_lo,  g_wT_lo);

    cudaFuncSetAttribute(gemm_pro,                cudaFuncAttributeMaxDynamicSharedMemorySize, SMEM_BYTES);
    cudaFuncSetAttribute(gemm_mma<0,false,false>, cudaFuncAttributeMaxDynamicSharedMemorySize, SMEM_BYTES);
    cudaFuncSetAttribute(gemm_mma<0,false,true >, cudaFuncAttributeMaxDynamicSharedMemorySize, SMEM_BYTES);
    cudaFuncSetAttribute(gemm_mma<2,true ,true >, cudaFuncAttributeMaxDynamicSharedMemorySize, SMEM_BYTES);
    cudaFuncSetAttribute(gemm_mma<1,false,false>, cudaFuncAttributeMaxDynamicSharedMemorySize, SMEM_BYTES);

    // weight slots: 0 Wd, 1 Whq0 (merged N=1024), 2 We, 3 Wtk, 4 Wtout0, 5 Wtout1,
    //               6 Whk, 7 Wh, 8 Whq1 (7/8 consumed by hist_small)
    WPtrs wp;
    wp.s[0] = W_tq;               wp.s[1] = W_hq;               wp.s[2] = W_tq + 1024LL*512;
    wp.s[3] = W_tk;               wp.s[4] = W_tout;             wp.s[5] = W_tout + 512LL*512;
    wp.s[6] = W_hk;               wp.s[7] = W_tq + 512LL*512;   wp.s[8] = W_hq + 512LL*512;
    #define WTH(i) (wT_hi + (long long)(i)*512*512)
    #define WTL(i) (wT_lo + (long long)(i)*512*512)

    detect_mask_kernel<<<1, 256>>>((const unsigned int*)adj, 65536);
    prep_weights<<<dim3(16,16,9), dim3(32,8)>>>(wp, wT_hi, wT_lo);

    const __nv_bfloat16* nb = nullptr;

    // hh = history @ [Wh | Whq1]  (8 x 1024)
    hist_small<<<128, 256>>>(history, WTH(7), WTL(7), WTH(8), WTL(8), hh);
    // prologue uber-GEMM: dh + headq + tk in one launch (320 CTAs)
    gemm_pro<<<320, 256, SMEM_BYTES>>>(dec_out, emb, head, tail, wT_hi, wT_lo,
                                       dh, headq, tk_hi, tk_lo, b_tk);
    transpose_tk<<<dim3(16,16,8), dim3(32,8)>>>(tk_hi, tk_lo, tkT_hi, tkT_lo);
    build_tq<<<8192, 256>>>((const float4*)dh, (const float4*)hh,
                            (const float4*)headq, (const float4*)b_tq,
                            (__nv_bfloat162*)tq_hi, (__nv_bfloat162*)tq_lo);
    // scores[b] = tq[b] @ tk[b]^T  (M=2048 per batch)
    gemm_mma<0,false,false><<<dim3(4,32,8), 256, SMEM_BYTES>>>(
        tq_hi, tq_lo, tk_hi, tk_lo, nb, nb, nb, nb,
        attn, nullptr, nullptr, nullptr, 2048, 512,
        2048LL*512, 512LL*512, 2048LL*512, 512);
    masked_softmax<<<dim3(2048,8), 256>>>(attn, at_hi, at_lo, adj, dup);
    // ctx[b] = attn[b] @ tk[b] -> bf16
    gemm_mma<0,false,true><<<dim3(4,32,8), 256, SMEM_BYTES>>>(
        at_hi, at_lo, tkT_hi, tkT_lo, nb, nb, nb, nb,
        nullptr, ctx_hi, ctx_lo, nullptr, 2048, 512,
        2048LL*512, 512LL*512, 2048LL*512, 512);
    // ghid = tanh(ctx @ Wtout0 + tq @ Wtout1) -> bf16 (M=16384)
    gemm_mma<2,true,true><<<dim3(4,256,1), 256, SMEM_BYTES>>>(
        ctx_hi, ctx_lo, WTH(4), WTL(4),
        tq_hi, tq_lo, WTH(5), WTL(5),
        nullptr, gh_hi, gh_lo, nullptr, 16384, 512, 0, 0, 0, 512);
    // hk = elu(ghid @ Whk + b_hk) (M=16384, fp32)
    gemm_mma<1,false,false><<<dim3(4,256,1), 256, SMEM_BYTES>>>(
        gh_hi, gh_lo, WTH(6), WTL(6), nb, nb, nb, nb,
        hk, nullptr, nullptr, b_hk, 16384, 512, 0, 0, 0, 512);
    build_hq<<<128, 256>>>((const float4*)dh, (const float4*)hh,
                           (const float4*)b_hq, (float4*)hq);
    final_kernel<<<256, 256>>>(hq, hk, attn, head, (float*)d_out);
}